// round 4
// baseline (speedup 1.0000x reference)
#include <cuda_runtime.h>
#include <cuda_fp16.h>
#include <cstdint>
#include <math.h>

#define BATCH 2
#define NPTS  4096
#define CDIM  128
#define TOPK  8
#define ITERS 15
#define CSTRIDE 4112

// ---------------------------------------------------------------------------
// Device scratch
// ---------------------------------------------------------------------------
__device__ __half g_E[(size_t)BATCH * NPTS * NPTS];   // exp(scores), 67 MB
__device__ __half g_hA[BATCH * NPTS * CDIM];
__device__ __half g_hB[BATCH * NPTS * CDIM];
__device__ float  g_r[BATCH * CSTRIDE];
__device__ float  g_c[BATCH * CSTRIDE];
__device__ float  g_colsum[BATCH * NPTS];
__device__ float  g_rsumA[ITERS * BATCH];        // sum_i r_i at iter it
__device__ float  g_sumcA[(ITERS + 1) * BATCH];  // sum_{j<N} c_j of c^(it-1)
__device__ float  g_cNa[(ITERS + 1) * BATCH];    // dust-col scale c_N^(it-1)
__device__ float  g_posBx[BATCH * NPTS];
__device__ float  g_posBy[BATCH * NPTS];
__device__ float  g_conf[BATCH * NPTS];
__device__ float  g_base[BATCH * NPTS * 2];
__device__ int    g_tki[BATCH * NPTS * TOPK];
__device__ float  g_tkl[BATCH * NPTS * TOPK];
__device__ float  g_geo[BATCH * NPTS * TOPK];
__device__ float  g_params[4];

// ---------------------------------------------------------------------------
// FMA-pipe exp (no MUFU)
// ---------------------------------------------------------------------------
__device__ __forceinline__ float fexpf(float x) {
    float t = x * 1.4426950408889634f;
    float z = t + 12582912.0f;
    int   ni = __float_as_int(z);
    float n  = z - 12582912.0f;
    float f  = t - n;
    float p = 1.5403530e-4f;
    p = fmaf(p, f, 1.33335581e-3f);
    p = fmaf(p, f, 9.61812911e-3f);
    p = fmaf(p, f, 5.55041087e-2f);
    p = fmaf(p, f, 2.40226507e-1f);
    p = fmaf(p, f, 6.93147181e-1f);
    p = fmaf(p, f, 1.0f);
    int e = (ni & 0x7FFFFF) - 0x400000;
    float s = __int_as_float((e + 127) << 23);
    return p * s;
}

// ---------------------------------------------------------------------------
// Prep
// ---------------------------------------------------------------------------
__global__ void prep_kernel(const float* __restrict__ dust,
                            const float* __restrict__ geow,
                            const float* __restrict__ temp,
                            const float* __restrict__ posB) {
    int t = blockIdx.x * 256 + threadIdx.x;
    if (t == 0) {
        float tr = temp[0];
        g_params[0] = 1.0f / tr;
        float tc = fminf(fmaxf(tr, 0.2f), 10.0f);
        float ds = fminf(fmaxf(dust[0] / tc, -50.0f), 50.0f);
        g_params[1] = expf(ds);
        g_params[2] = fminf(fmaxf(geow[0], 0.0f), 2.0f);
    }
    if (t < BATCH * CSTRIDE) g_c[t] = 1.0f;
    if (t < BATCH * NPTS) {
        g_colsum[t] = 0.0f;
        g_posBx[t] = posB[2 * t];
        g_posBy[t] = posB[2 * t + 1];
    }
    if (t < ITERS * BATCH) g_rsumA[t] = 0.0f;
    if (t < (ITERS + 1) * BATCH) {
        g_sumcA[t] = (t < BATCH) ? 4096.0f : 0.0f;
        g_cNa[t]   = (t < BATCH) ? 1.0f    : 0.0f;
    }
}

// ---------------------------------------------------------------------------
// L2-normalize -> fp16 features
// ---------------------------------------------------------------------------
__global__ void norm_kernel(const float* __restrict__ fA, const float* __restrict__ fB) {
    int wg   = blockIdx.x * 8 + (threadIdx.x >> 5);
    int lane = threadIdx.x & 31;
    int tensor = wg >> 13;
    int row    = wg & 8191;
    const float* src = tensor ? fB : fA;
    __half*      dst = tensor ? g_hB : g_hA;
    float4 v = *reinterpret_cast<const float4*>(src + (size_t)row * CDIM + lane * 4);
    float ss = v.x * v.x + v.y * v.y + v.z * v.z + v.w * v.w;
#pragma unroll
    for (int o = 16; o; o >>= 1) ss += __shfl_xor_sync(0xffffffffu, ss, o);
    float inv = 1.0f / fmaxf(sqrtf(ss), 1e-12f);
    __half2 h01 = __floats2half2_rn(v.x * inv, v.y * inv);
    __half2 h23 = __floats2half2_rn(v.z * inv, v.w * inv);
    uint2 u;
    u.x = *reinterpret_cast<uint32_t*>(&h01);
    u.y = *reinterpret_cast<uint32_t*>(&h23);
    *reinterpret_cast<uint2*>(dst + (size_t)row * CDIM + lane * 4) = u;
}

// ---------------------------------------------------------------------------
// Tensor-core GEMM + exp epilogue (unchanged from round 3)
// ---------------------------------------------------------------------------
__device__ __forceinline__ void ldsm4(uint32_t* r, uint32_t addr) {
    asm volatile("ldmatrix.sync.aligned.m8n8.x4.shared.b16 {%0,%1,%2,%3}, [%4];\n"
        : "=r"(r[0]), "=r"(r[1]), "=r"(r[2]), "=r"(r[3]) : "r"(addr));
}
__device__ __forceinline__ void mma16816(float* c, const uint32_t* a, const uint32_t* b) {
    asm volatile("mma.sync.aligned.m16n8k16.row.col.f32.f16.f16.f32 "
        "{%0,%1,%2,%3}, {%4,%5,%6,%7}, {%8,%9}, {%0,%1,%2,%3};\n"
        : "+f"(c[0]), "+f"(c[1]), "+f"(c[2]), "+f"(c[3])
        : "r"(a[0]), "r"(a[1]), "r"(a[2]), "r"(a[3]), "r"(b[0]), "r"(b[1]));
}

#define SMK 72
#define SOUTS 136

__global__ __launch_bounds__(256) void gemm_exp_kernel() {
    int b  = blockIdx.z;
    int i0 = blockIdx.y * 128;
    int j0 = blockIdx.x * 128;
    const __half* A  = g_hA + (size_t)b * NPTS * CDIM;
    const __half* Bm = g_hB + (size_t)b * NPTS * CDIM;

    __shared__ __align__(16) __half smem[2 * 128 * SMK];
    __half* sA = smem;
    __half* sB = smem + 128 * SMK;

    int tid = threadIdx.x;
    int w = tid >> 5, lane = tid & 31;
    int wm = (w >> 1) * 32, wn = (w & 1) * 64;
    float itp = g_params[0];

    float acc[2][8][4];
#pragma unroll
    for (int mt = 0; mt < 2; mt++)
#pragma unroll
        for (int nt = 0; nt < 8; nt++)
#pragma unroll
            for (int q = 0; q < 4; q++) acc[mt][nt][q] = 0.0f;

#pragma unroll
    for (int kb = 0; kb < CDIM; kb += 64) {
        if (kb) __syncthreads();
#pragma unroll
        for (int e = 0; e < 4; e++) {
            int idx = tid + e * 256;
            int r = idx >> 3, c8 = idx & 7;
            *reinterpret_cast<uint4*>(sA + r * SMK + c8 * 8) =
                *reinterpret_cast<const uint4*>(A + (size_t)(i0 + r) * CDIM + kb + c8 * 8);
            *reinterpret_cast<uint4*>(sB + r * SMK + c8 * 8) =
                *reinterpret_cast<const uint4*>(Bm + (size_t)(j0 + r) * CDIM + kb + c8 * 8);
        }
        __syncthreads();

#pragma unroll
        for (int ks = 0; ks < 4; ks++) {
            int k0 = ks * 16;
            uint32_t afr[2][4];
#pragma unroll
            for (int mt = 0; mt < 2; mt++) {
                int row = wm + mt * 16 + (lane & 15);
                int col = k0 + ((lane >> 4) << 3);
                uint32_t addr = (uint32_t)__cvta_generic_to_shared(sA + row * SMK + col);
                ldsm4(afr[mt], addr);
            }
            uint32_t bfr[8][2];
#pragma unroll
            for (int p = 0; p < 4; p++) {
                int l4 = lane & 7, g = lane >> 3;
                int row = wn + p * 16 + ((g >> 1) << 3) + l4;
                int col = k0 + ((g & 1) << 3);
                uint32_t addr = (uint32_t)__cvta_generic_to_shared(sB + row * SMK + col);
                uint32_t t4[4];
                ldsm4(t4, addr);
                bfr[2 * p][0] = t4[0]; bfr[2 * p][1] = t4[1];
                bfr[2 * p + 1][0] = t4[2]; bfr[2 * p + 1][1] = t4[3];
            }
#pragma unroll
            for (int mt = 0; mt < 2; mt++)
#pragma unroll
                for (int nt = 0; nt < 8; nt++)
                    mma16816(acc[mt][nt], afr[mt], bfr[nt]);
        }
    }
    __syncthreads();

    __half* sO = smem;
#pragma unroll
    for (int mt = 0; mt < 2; mt++) {
#pragma unroll
        for (int nt = 0; nt < 8; nt++) {
            float e0 = fexpf(fminf(fmaxf(acc[mt][nt][0] * itp, -50.0f), 50.0f));
            float e1 = fexpf(fminf(fmaxf(acc[mt][nt][1] * itp, -50.0f), 50.0f));
            float e2 = fexpf(fminf(fmaxf(acc[mt][nt][2] * itp, -50.0f), 50.0f));
            float e3 = fexpf(fminf(fmaxf(acc[mt][nt][3] * itp, -50.0f), 50.0f));
            int row  = wm + mt * 16 + (lane >> 2);
            int colh = wn + nt * 8 + ((lane & 3) << 1);
            *reinterpret_cast<__half2*>(sO + row * SOUTS + colh)       = __floats2half2_rn(e0, e1);
            *reinterpret_cast<__half2*>(sO + (row + 8) * SOUTS + colh) = __floats2half2_rn(e2, e3);
        }
    }
    __syncthreads();

    __half* Eb = g_E + ((size_t)b << 24);
#pragma unroll
    for (int e = 0; e < 8; e++) {
        int idx = tid + e * 256;
        int r = idx >> 4, c = idx & 15;
        *reinterpret_cast<uint4*>(Eb + (size_t)(i0 + r) * NPTS + j0 + c * 8) =
            *reinterpret_cast<uint4*>(sO + r * SOUTS + c * 8);
    }
}

// ---------------------------------------------------------------------------
// Fused Sinkhorn iteration: 16-row stripes, grid (256, BATCH) x 256 threads.
// phase1: r for 16 rows; phase2: E^T r partials for the stripe (L2-hot).
// ---------------------------------------------------------------------------
__global__ __launch_bounds__(256) void sink_fused(int it) {
    int b = blockIdx.y;
    int i0 = blockIdx.x * 16;
    int tid = threadIdx.x, w = tid >> 5, lane = tid & 31;
    __shared__ __align__(16) float cs[4100];
    __shared__ float rs[16];
    const float* cg = g_c + b * CSTRIDE;
#pragma unroll
    for (int q = 0; q < 16; q++) cs[tid + q * 256] = cg[tid + q * 256];
    __syncthreads();
    float ed = g_params[1];
    float cN = g_cNa[it * BATCH + b];
    const __half* Eb = g_E + ((size_t)b << 24);

    // phase 1: warp w handles rows i0 + 2w, 2w+1
#pragma unroll
    for (int rr = 0; rr < 2; rr++) {
        int i = i0 + w * 2 + rr;
        const __half* Er = Eb + ((size_t)i << 12);
        float sum = 0.0f;
#pragma unroll 4
        for (int c2 = 0; c2 < 16; c2++) {
            int j = c2 * 256 + lane * 8;
            uint4 ev = *reinterpret_cast<const uint4*>(Er + j);
            const __half2* hp = reinterpret_cast<const __half2*>(&ev);
            float4 c0 = *reinterpret_cast<const float4*>(cs + j);
            float4 c1 = *reinterpret_cast<const float4*>(cs + j + 4);
            float2 f0 = __half22float2(hp[0]);
            float2 f1 = __half22float2(hp[1]);
            float2 f2 = __half22float2(hp[2]);
            float2 f3 = __half22float2(hp[3]);
            sum = fmaf(f0.x, c0.x, sum); sum = fmaf(f0.y, c0.y, sum);
            sum = fmaf(f1.x, c0.z, sum); sum = fmaf(f1.y, c0.w, sum);
            sum = fmaf(f2.x, c1.x, sum); sum = fmaf(f2.y, c1.y, sum);
            sum = fmaf(f3.x, c1.z, sum); sum = fmaf(f3.y, c1.w, sum);
        }
#pragma unroll
        for (int o = 16; o; o >>= 1) sum += __shfl_xor_sync(0xffffffffu, sum, o);
        if (lane == 0) {
            float r = (1.0f / 8192.0f) / (sum + ed * cN);
            rs[w * 2 + rr] = r;
            g_r[b * CSTRIDE + i] = r;
        }
    }
    __syncthreads();
    if (tid < 16) {
        float v = rs[tid];
#pragma unroll
        for (int o = 8; o; o >>= 1) v += __shfl_xor_sync(0xffffu, v, o);
        if (tid == 0) atomicAdd(&g_rsumA[it * BATCH + b], v);
    }

    // phase 2: thread owns cols tid*16..+15, loops 16 stripe rows (L2-hot)
    float a[16];
#pragma unroll
    for (int q = 0; q < 16; q++) a[q] = 0.0f;
    const __half* Ec = Eb + ((size_t)i0 << 12) + tid * 16;
#pragma unroll 4
    for (int i = 0; i < 16; i++) {
        const __half* row = Ec + ((size_t)i << 12);
        uint4 e0 = *reinterpret_cast<const uint4*>(row);
        uint4 e1 = *reinterpret_cast<const uint4*>(row + 8);
        float r = rs[i];
        const __half2* h0 = reinterpret_cast<const __half2*>(&e0);
        const __half2* h1 = reinterpret_cast<const __half2*>(&e1);
#pragma unroll
        for (int q = 0; q < 4; q++) {
            float2 f = __half22float2(h0[q]);
            a[2 * q]     = fmaf(f.x, r, a[2 * q]);
            a[2 * q + 1] = fmaf(f.y, r, a[2 * q + 1]);
            float2 g = __half22float2(h1[q]);
            a[8 + 2 * q]     = fmaf(g.x, r, a[8 + 2 * q]);
            a[8 + 2 * q + 1] = fmaf(g.y, r, a[8 + 2 * q + 1]);
        }
    }
    float* col = g_colsum + b * NPTS + tid * 16;
#pragma unroll
    for (int q = 0; q < 16; q++) atomicAdd(col + q, a[q]);
}

// ---------------------------------------------------------------------------
// Finish: c update from colsum, per-iteration scalars.  grid (16, BATCH).
// ---------------------------------------------------------------------------
__global__ __launch_bounds__(256) void sink_finish(int it) {
    int b = blockIdx.y, tid = threadIdx.x;
    int j = blockIdx.x * 256 + tid;
    float ed = g_params[1];
    float rm = 0.5f / (ed * g_sumcA[it * BATCH + b] + g_cNa[it * BATCH + b]);
    float* col = g_colsum + b * NPTS;
    float v = col[j];
    col[j] = 0.0f;
    float cj = (1.0f / 8192.0f) / (v + ed * rm);
    g_c[b * CSTRIDE + j] = cj;
    // block-reduce sum of cj -> sumcA[it+1]
    float s = cj;
#pragma unroll
    for (int o = 16; o; o >>= 1) s += __shfl_xor_sync(0xffffffffu, s, o);
    __shared__ float red[8];
    if ((tid & 31) == 0) red[tid >> 5] = s;
    __syncthreads();
    if (tid == 0) {
        float tot = 0.0f;
#pragma unroll
        for (int ww = 0; ww < 8; ww++) tot += red[ww];
        atomicAdd(&g_sumcA[(it + 1) * BATCH + b], tot);
        if (blockIdx.x == 0)
            g_cNa[(it + 1) * BATCH + b] = 0.5f / (ed * g_rsumA[it * BATCH + b] + rm);
    }
}

// ---------------------------------------------------------------------------
// Per-row stats (unchanged)
// ---------------------------------------------------------------------------
__global__ void stats_kernel() {
    int b = blockIdx.y, i = blockIdx.x, tid = threadIdx.x;
    const __half* Er = g_E + ((size_t)b << 24) + ((size_t)i << 12);
    const float* cb  = g_c + b * CSTRIDE;
    const float* pxb = g_posBx + b * NPTS;
    const float* pyb = g_posBy + b * NPTS;
    float rp = g_r[b * CSTRIDE + i];

    float sm = 0.0f, sx = 0.0f, sy = 0.0f;
    float tv[8]; int tix[8];
#pragma unroll
    for (int t = 0; t < 8; t++) { tv[t] = -1.0f; tix[t] = 0x7fffffff; }

#pragma unroll
    for (int it = 0; it < 2; ++it) {
        int j = it * 2048 + tid * 8;
        uint4 ev = *reinterpret_cast<const uint4*>(Er + j);
        const __half2* hp = reinterpret_cast<const __half2*>(&ev);
        float4 c0 = *reinterpret_cast<const float4*>(cb + j);
        float4 c1 = *reinterpret_cast<const float4*>(cb + j + 4);
        float4 x0 = *reinterpret_cast<const float4*>(pxb + j);
        float4 x1 = *reinterpret_cast<const float4*>(pxb + j + 4);
        float4 y0 = *reinterpret_cast<const float4*>(pyb + j);
        float4 y1 = *reinterpret_cast<const float4*>(pyb + j + 4);
        float2 f0 = __half22float2(hp[0]);
        float2 f1 = __half22float2(hp[1]);
        float2 f2 = __half22float2(hp[2]);
        float2 f3 = __half22float2(hp[3]);
        float ps[8] = {f0.x, f0.y, f1.x, f1.y, f2.x, f2.y, f3.x, f3.y};
        float csv[8] = {c0.x, c0.y, c0.z, c0.w, c1.x, c1.y, c1.z, c1.w};
        float xs[8] = {x0.x, x0.y, x0.z, x0.w, x1.x, x1.y, x1.z, x1.w};
        float ys[8] = {y0.x, y0.y, y0.z, y0.w, y1.x, y1.y, y1.z, y1.w};
#pragma unroll
        for (int q = 0; q < 8; q++) {
            float P  = ps[q] * rp * csv[q];
            float ot = fminf(P, 1.0f);
            sm += ot;
            sx = fmaf(ot, xs[q], sx);
            sy = fmaf(ot, ys[q], sy);
            int jj = j + q;
            if (ot > tv[7] || (ot == tv[7] && jj < tix[7])) {
                tv[7] = ot; tix[7] = jj;
#pragma unroll
                for (int q2 = 7; q2 > 0; --q2) {
                    bool sw = (tv[q2] > tv[q2 - 1]) ||
                              (tv[q2] == tv[q2 - 1] && tix[q2] < tix[q2 - 1]);
                    if (sw) {
                        float fv = tv[q2]; tv[q2] = tv[q2 - 1]; tv[q2 - 1] = fv;
                        int ii = tix[q2]; tix[q2] = tix[q2 - 1]; tix[q2 - 1] = ii;
                    }
                }
            }
        }
    }

    float s0 = sm, s1 = sx, s2 = sy;
#pragma unroll
    for (int o = 16; o; o >>= 1) {
        s0 += __shfl_xor_sync(0xffffffffu, s0, o);
        s1 += __shfl_xor_sync(0xffffffffu, s1, o);
        s2 += __shfl_xor_sync(0xffffffffu, s2, o);
    }
    __shared__ float redm[8], redx[8], redy[8];
    if ((tid & 31) == 0) { redm[tid >> 5] = s0; redx[tid >> 5] = s1; redy[tid >> 5] = s2; }

    __shared__ float sv[2048];
    __shared__ int   si[2048];
#pragma unroll
    for (int t = 0; t < 8; t++) { sv[tid * 8 + t] = tv[t]; si[tid * 8 + t] = tix[t]; }
    __syncthreads();

    for (int step = 128; step >= 1; step >>= 1) {
        if (tid < step) {
            int ia = tid * 8, ib = (tid + step) * 8;
            float av[8], bv[8], ov[8]; int ai[8], bi[8], oi[8];
#pragma unroll
            for (int t = 0; t < 8; t++) {
                av[t] = sv[ia + t]; ai[t] = si[ia + t];
                bv[t] = sv[ib + t]; bi[t] = si[ib + t];
            }
            int pa = 0, pb = 0;
#pragma unroll
            for (int o = 0; o < 8; o++) {
                bool ta = (av[pa] > bv[pb]) || (av[pa] == bv[pb] && ai[pa] <= bi[pb]);
                if (ta) { ov[o] = av[pa]; oi[o] = ai[pa]; pa++; }
                else    { ov[o] = bv[pb]; oi[o] = bi[pb]; pb++; }
            }
#pragma unroll
            for (int t = 0; t < 8; t++) { sv[ia + t] = ov[t]; si[ia + t] = oi[t]; }
        }
        __syncthreads();
    }

    if (tid == 0) {
        float smT = 0, sxT = 0, syT = 0;
#pragma unroll
        for (int w = 0; w < 8; w++) { smT += redm[w]; sxT += redx[w]; syT += redy[w]; }
        float rmass = fmaxf(smT, 1e-8f);
        float valid = fminf(fmaxf(rmass * 8192.0f, 0.0f), 1.0f);
        float top1 = sv[0], top2 = sv[1];
        float pr = fminf(fmaxf(top1 / rmass, 0.0f), 1.0f);
        float pm = fminf(fmaxf((top1 - top2) / rmass, 0.0f), 1.0f);
        float conf = fminf(fmaxf((0.6f * pr + 0.4f * pm) * valid, 0.0f), 1.0f);
        int o = b * NPTS + i;
        g_conf[o] = conf;
        g_base[o * 2]     = sxT / rmass;
        g_base[o * 2 + 1] = syT / rmass;
#pragma unroll
        for (int k = 0; k < 8; k++) {
            g_tki[o * 8 + k] = si[k];
            g_tkl[o * 8 + k] = logf(fmaxf(sv[k], 1e-38f));
        }
    }
}

// ---------------------------------------------------------------------------
// Geo validation (unchanged)
// ---------------------------------------------------------------------------
__global__ void geo_kernel(const float* __restrict__ posA) {
    int bk = blockIdx.x;
    int b = bk >> 3, k = bk & 7;
    int tid = threadIdx.x;
    __shared__ float dx[NPTS], dy[NPTS];
    for (int n = tid; n < NPTS; n += 256) {
        int idx = g_tki[(b * NPTS + n) * 8 + k];
        float ax = posA[(size_t)(b * NPTS + n) * 2];
        float ay = posA[(size_t)(b * NPTS + n) * 2 + 1];
        dx[n] = g_posBx[b * NPTS + idx] - ax;
        dy[n] = g_posBy[b * NPTS + idx] - ay;
    }
    __syncthreads();
    for (int n = tid; n < NPTS; n += 256) {
        int h = n >> 6, w = n & 63;
        int h0 = max(h - 3, 0), h1 = min(h + 3, 63);
        int w0 = max(w - 3, 0), w1 = min(w + 3, 63);
        float sxv = 0, syv = 0, sxx = 0, syy = 0;
        for (int hh = h0; hh <= h1; hh++) {
            int base = hh * 64;
            for (int ww = w0; ww <= w1; ww++) {
                float vx = dx[base + ww], vy = dy[base + ww];
                sxv += vx; syv += vy;
                sxx = fmaf(vx, vx, sxx);
                syy = fmaf(vy, vy, syy);
            }
        }
        float inv = 1.0f / (float)((h1 - h0 + 1) * (w1 - w0 + 1));
        float mx = sxv * inv, my = syv * inv;
        float vx = fmaxf(sxx * inv - mx * mx, 0.0f);
        float vy = fmaxf(syy * inv - my * my, 0.0f);
        g_geo[(b * NPTS + n) * 8 + k] = 1.0f / (1.0f + (vx + vy) * 100.0f);
    }
}

// ---------------------------------------------------------------------------
// Final blend (unchanged)
// ---------------------------------------------------------------------------
__global__ void final_kernel(float* __restrict__ out) {
    int t = blockIdx.x * 128 + threadIdx.x;
    int b = t >> 12, n = t & 4095;
    int o = b * NPTS + n;
    float gwv = g_params[2];
    float lc[8]; int id[8];
    float m = -1e30f;
#pragma unroll
    for (int k = 0; k < 8; k++) {
        lc[k] = g_tkl[o * 8 + k] + gwv * g_geo[o * 8 + k];
        id[k] = g_tki[o * 8 + k];
        m = fmaxf(m, lc[k]);
    }
    float ws = 0, rx = 0, ry = 0;
#pragma unroll
    for (int k = 0; k < 8; k++) {
        float w = fexpf(fmaxf(lc[k] - m, -80.0f));
        ws += w;
        rx = fmaf(w, g_posBx[b * NPTS + id[k]], rx);
        ry = fmaf(w, g_posBy[b * NPTS + id[k]], ry);
    }
    rx /= ws; ry /= ws;
    float conf = g_conf[o];
    out[o * 2]     = conf * rx + (1.0f - conf) * g_base[o * 2];
    out[o * 2 + 1] = conf * ry + (1.0f - conf) * g_base[o * 2 + 1];
}

// ---------------------------------------------------------------------------
extern "C" void kernel_launch(void* const* d_in, const int* in_sizes, int n_in,
                              void* d_out, int out_size) {
    const float* fA   = (const float*)d_in[0];
    const float* fB   = (const float*)d_in[1];
    const float* pA   = (const float*)d_in[2];
    const float* pB   = (const float*)d_in[3];
    const float* dust = (const float*)d_in[4];
    const float* geow = (const float*)d_in[5];
    const float* temp = (const float*)d_in[6];
    float* out = (float*)d_out;

    prep_kernel<<<33, 256>>>(dust, geow, temp, pB);
    norm_kernel<<<2048, 256>>>(fA, fB);
    gemm_exp_kernel<<<dim3(32, 32, BATCH), 256>>>();
    for (int it = 0; it < ITERS; ++it) {
        sink_fused<<<dim3(256, BATCH), 256>>>(it);
        sink_finish<<<dim3(16, BATCH), 256>>>(it);
    }
    stats_kernel<<<dim3(NPTS, BATCH), 256>>>();
    geo_kernel<<<BATCH * TOPK, 256>>>(pA);
    final_kernel<<<64, 128>>>(out);
}

// round 5
// speedup vs baseline: 1.2232x; 1.2232x over previous
#include <cuda_runtime.h>
#include <cuda_fp16.h>
#include <cstdint>
#include <math.h>

#define BATCH 2
#define NPTS  4096
#define CDIM  128
#define TOPK  8
#define ITERS 15
#define CSTRIDE 4112
#define STRIPE 16
#define NSTRIPES (NPTS / STRIPE)   // 256

// ---------------------------------------------------------------------------
// Device scratch
// ---------------------------------------------------------------------------
__device__ __half g_E[(size_t)BATCH * NPTS * NPTS];   // exp(scores), 67 MB
__device__ __half g_hA[BATCH * NPTS * CDIM];
__device__ __half g_hB[BATCH * NPTS * CDIM];
__device__ float  g_r[BATCH * CSTRIDE];
__device__ float  g_c[BATCH * CSTRIDE];
__device__ float  g_colpart[BATCH * NSTRIPES * NPTS];   // 8 MB, per-stripe col partials
__device__ float  g_rsumA[ITERS * BATCH];
__device__ float  g_sumcA[(ITERS + 1) * BATCH];
__device__ float  g_cNa[(ITERS + 1) * BATCH];
__device__ float  g_posBx[BATCH * NPTS];
__device__ float  g_posBy[BATCH * NPTS];
__device__ float  g_conf[BATCH * NPTS];
__device__ float  g_base[BATCH * NPTS * 2];
__device__ int    g_tki[BATCH * NPTS * TOPK];
__device__ float  g_tkl[BATCH * NPTS * TOPK];
__device__ float  g_geo[BATCH * NPTS * TOPK];
__device__ float  g_params[4];

// ---------------------------------------------------------------------------
// FMA-pipe exp (no MUFU)
// ---------------------------------------------------------------------------
__device__ __forceinline__ float fexpf(float x) {
    float t = x * 1.4426950408889634f;
    float z = t + 12582912.0f;
    int   ni = __float_as_int(z);
    float n  = z - 12582912.0f;
    float f  = t - n;
    float p = 1.5403530e-4f;
    p = fmaf(p, f, 1.33335581e-3f);
    p = fmaf(p, f, 9.61812911e-3f);
    p = fmaf(p, f, 5.55041087e-2f);
    p = fmaf(p, f, 2.40226507e-1f);
    p = fmaf(p, f, 6.93147181e-1f);
    p = fmaf(p, f, 1.0f);
    int e = (ni & 0x7FFFFF) - 0x400000;
    float s = __int_as_float((e + 127) << 23);
    return p * s;
}

// ---------------------------------------------------------------------------
// Prep
// ---------------------------------------------------------------------------
__global__ void prep_kernel(const float* __restrict__ dust,
                            const float* __restrict__ geow,
                            const float* __restrict__ temp,
                            const float* __restrict__ posB) {
    int t = blockIdx.x * 256 + threadIdx.x;
    if (t == 0) {
        float tr = temp[0];
        g_params[0] = 1.0f / tr;
        float tc = fminf(fmaxf(tr, 0.2f), 10.0f);
        float ds = fminf(fmaxf(dust[0] / tc, -50.0f), 50.0f);
        g_params[1] = expf(ds);
        g_params[2] = fminf(fmaxf(geow[0], 0.0f), 2.0f);
    }
    if (t < BATCH * CSTRIDE) g_c[t] = 1.0f;
    if (t < BATCH * NPTS) {
        g_posBx[t] = posB[2 * t];
        g_posBy[t] = posB[2 * t + 1];
    }
    if (t < ITERS * BATCH) g_rsumA[t] = 0.0f;
    if (t < (ITERS + 1) * BATCH) {
        g_sumcA[t] = (t < BATCH) ? 4096.0f : 0.0f;
        g_cNa[t]   = (t < BATCH) ? 1.0f    : 0.0f;
    }
}

// ---------------------------------------------------------------------------
// L2-normalize -> fp16 features
// ---------------------------------------------------------------------------
__global__ void norm_kernel(const float* __restrict__ fA, const float* __restrict__ fB) {
    int wg   = blockIdx.x * 8 + (threadIdx.x >> 5);
    int lane = threadIdx.x & 31;
    int tensor = wg >> 13;
    int row    = wg & 8191;
    const float* src = tensor ? fB : fA;
    __half*      dst = tensor ? g_hB : g_hA;
    float4 v = *reinterpret_cast<const float4*>(src + (size_t)row * CDIM + lane * 4);
    float ss = v.x * v.x + v.y * v.y + v.z * v.z + v.w * v.w;
#pragma unroll
    for (int o = 16; o; o >>= 1) ss += __shfl_xor_sync(0xffffffffu, ss, o);
    float inv = 1.0f / fmaxf(sqrtf(ss), 1e-12f);
    __half2 h01 = __floats2half2_rn(v.x * inv, v.y * inv);
    __half2 h23 = __floats2half2_rn(v.z * inv, v.w * inv);
    uint2 u;
    u.x = *reinterpret_cast<uint32_t*>(&h01);
    u.y = *reinterpret_cast<uint32_t*>(&h23);
    *reinterpret_cast<uint2*>(dst + (size_t)row * CDIM + lane * 4) = u;
}

// ---------------------------------------------------------------------------
// Tensor-core GEMM + exp epilogue (unchanged)
// ---------------------------------------------------------------------------
__device__ __forceinline__ void ldsm4(uint32_t* r, uint32_t addr) {
    asm volatile("ldmatrix.sync.aligned.m8n8.x4.shared.b16 {%0,%1,%2,%3}, [%4];\n"
        : "=r"(r[0]), "=r"(r[1]), "=r"(r[2]), "=r"(r[3]) : "r"(addr));
}
__device__ __forceinline__ void mma16816(float* c, const uint32_t* a, const uint32_t* b) {
    asm volatile("mma.sync.aligned.m16n8k16.row.col.f32.f16.f16.f32 "
        "{%0,%1,%2,%3}, {%4,%5,%6,%7}, {%8,%9}, {%0,%1,%2,%3};\n"
        : "+f"(c[0]), "+f"(c[1]), "+f"(c[2]), "+f"(c[3])
        : "r"(a[0]), "r"(a[1]), "r"(a[2]), "r"(a[3]), "r"(b[0]), "r"(b[1]));
}

#define SMK 72
#define SOUTS 136

__global__ __launch_bounds__(256) void gemm_exp_kernel() {
    int b  = blockIdx.z;
    int i0 = blockIdx.y * 128;
    int j0 = blockIdx.x * 128;
    const __half* A  = g_hA + (size_t)b * NPTS * CDIM;
    const __half* Bm = g_hB + (size_t)b * NPTS * CDIM;

    __shared__ __align__(16) __half smem[2 * 128 * SMK];
    __half* sA = smem;
    __half* sB = smem + 128 * SMK;

    int tid = threadIdx.x;
    int w = tid >> 5, lane = tid & 31;
    int wm = (w >> 1) * 32, wn = (w & 1) * 64;
    float itp = g_params[0];

    float acc[2][8][4];
#pragma unroll
    for (int mt = 0; mt < 2; mt++)
#pragma unroll
        for (int nt = 0; nt < 8; nt++)
#pragma unroll
            for (int q = 0; q < 4; q++) acc[mt][nt][q] = 0.0f;

#pragma unroll
    for (int kb = 0; kb < CDIM; kb += 64) {
        if (kb) __syncthreads();
#pragma unroll
        for (int e = 0; e < 4; e++) {
            int idx = tid + e * 256;
            int r = idx >> 3, c8 = idx & 7;
            *reinterpret_cast<uint4*>(sA + r * SMK + c8 * 8) =
                *reinterpret_cast<const uint4*>(A + (size_t)(i0 + r) * CDIM + kb + c8 * 8);
            *reinterpret_cast<uint4*>(sB + r * SMK + c8 * 8) =
                *reinterpret_cast<const uint4*>(Bm + (size_t)(j0 + r) * CDIM + kb + c8 * 8);
        }
        __syncthreads();

#pragma unroll
        for (int ks = 0; ks < 4; ks++) {
            int k0 = ks * 16;
            uint32_t afr[2][4];
#pragma unroll
            for (int mt = 0; mt < 2; mt++) {
                int row = wm + mt * 16 + (lane & 15);
                int col = k0 + ((lane >> 4) << 3);
                uint32_t addr = (uint32_t)__cvta_generic_to_shared(sA + row * SMK + col);
                ldsm4(afr[mt], addr);
            }
            uint32_t bfr[8][2];
#pragma unroll
            for (int p = 0; p < 4; p++) {
                int l4 = lane & 7, g = lane >> 3;
                int row = wn + p * 16 + ((g >> 1) << 3) + l4;
                int col = k0 + ((g & 1) << 3);
                uint32_t addr = (uint32_t)__cvta_generic_to_shared(sB + row * SMK + col);
                uint32_t t4[4];
                ldsm4(t4, addr);
                bfr[2 * p][0] = t4[0]; bfr[2 * p][1] = t4[1];
                bfr[2 * p + 1][0] = t4[2]; bfr[2 * p + 1][1] = t4[3];
            }
#pragma unroll
            for (int mt = 0; mt < 2; mt++)
#pragma unroll
                for (int nt = 0; nt < 8; nt++)
                    mma16816(acc[mt][nt], afr[mt], bfr[nt]);
        }
    }
    __syncthreads();

    __half* sO = smem;
#pragma unroll
    for (int mt = 0; mt < 2; mt++) {
#pragma unroll
        for (int nt = 0; nt < 8; nt++) {
            float e0 = fexpf(fminf(fmaxf(acc[mt][nt][0] * itp, -50.0f), 50.0f));
            float e1 = fexpf(fminf(fmaxf(acc[mt][nt][1] * itp, -50.0f), 50.0f));
            float e2 = fexpf(fminf(fmaxf(acc[mt][nt][2] * itp, -50.0f), 50.0f));
            float e3 = fexpf(fminf(fmaxf(acc[mt][nt][3] * itp, -50.0f), 50.0f));
            int row  = wm + mt * 16 + (lane >> 2);
            int colh = wn + nt * 8 + ((lane & 3) << 1);
            *reinterpret_cast<__half2*>(sO + row * SOUTS + colh)       = __floats2half2_rn(e0, e1);
            *reinterpret_cast<__half2*>(sO + (row + 8) * SOUTS + colh) = __floats2half2_rn(e2, e3);
        }
    }
    __syncthreads();

    __half* Eb = g_E + ((size_t)b << 24);
#pragma unroll
    for (int e = 0; e < 8; e++) {
        int idx = tid + e * 256;
        int r = idx >> 4, c = idx & 15;
        *reinterpret_cast<uint4*>(Eb + (size_t)(i0 + r) * NPTS + j0 + c * 8) =
            *reinterpret_cast<uint4*>(sO + r * SOUTS + c * 8);
    }
}

// ---------------------------------------------------------------------------
// Sinkhorn stripe kernel: 16 rows x 4096 cols staged in smem.
//   phase1 (fused with load): r_i for the 16 rows, E read from global ONCE.
//   phase2: column partials from smem -> g_colpart[stripe] (no atomics).
// grid (256, BATCH), 512 threads, 147456 B dynamic smem.
// ---------------------------------------------------------------------------
extern __shared__ __align__(16) unsigned char sk_smem[];

__global__ __launch_bounds__(512) void sink_stripe(int it) {
    int b = blockIdx.y;
    int i0 = blockIdx.x * STRIPE;
    int tid = threadIdx.x, w = tid >> 5, lane = tid & 31;
    float*  cs = reinterpret_cast<float*>(sk_smem);               // 16 KB
    __half* Es = reinterpret_cast<__half*>(sk_smem + NPTS * 4);   // 128 KB
    __shared__ float rs[STRIPE];

    const float* cg = g_c + b * CSTRIDE;
#pragma unroll
    for (int q = 0; q < 8; q++) cs[tid + q * 512] = cg[tid + q * 512];
    __syncthreads();

    float ed = g_params[1];
    float cN = g_cNa[it * BATCH + b];

    // phase 1: warp w owns row i0+w; load E row, FMA with c, stash raw E
    const __half* Er = g_E + ((size_t)b << 24) + ((size_t)(i0 + w) << 12);
    __half* Esr = Es + w * NPTS;
    float sum = 0.0f;
#pragma unroll 4
    for (int ch = 0; ch < 16; ch++) {
        int j = ch * 256 + lane * 8;
        uint4 ev = *reinterpret_cast<const uint4*>(Er + j);
        *reinterpret_cast<uint4*>(Esr + j) = ev;
        const __half2* hp = reinterpret_cast<const __half2*>(&ev);
        float4 c0 = *reinterpret_cast<const float4*>(cs + j);
        float4 c1 = *reinterpret_cast<const float4*>(cs + j + 4);
        float2 f0 = __half22float2(hp[0]);
        float2 f1 = __half22float2(hp[1]);
        float2 f2 = __half22float2(hp[2]);
        float2 f3 = __half22float2(hp[3]);
        sum = fmaf(f0.x, c0.x, sum); sum = fmaf(f0.y, c0.y, sum);
        sum = fmaf(f1.x, c0.z, sum); sum = fmaf(f1.y, c0.w, sum);
        sum = fmaf(f2.x, c1.x, sum); sum = fmaf(f2.y, c1.y, sum);
        sum = fmaf(f3.x, c1.z, sum); sum = fmaf(f3.y, c1.w, sum);
    }
#pragma unroll
    for (int o = 16; o; o >>= 1) sum += __shfl_xor_sync(0xffffffffu, sum, o);
    if (lane == 0) {
        float r = (1.0f / 8192.0f) / (sum + ed * cN);
        rs[w] = r;
        g_r[b * CSTRIDE + i0 + w] = r;
    }
    __syncthreads();

    if (tid < 16) {
        float v = rs[tid];
#pragma unroll
        for (int o = 8; o; o >>= 1) v += __shfl_xor_sync(0xffffu, v, o);
        if (tid == 0) atomicAdd(&g_rsumA[it * BATCH + b], v);
    }

    // phase 2: thread owns 8 cols, accumulate over the 16 smem rows
    float a[8];
#pragma unroll
    for (int q = 0; q < 8; q++) a[q] = 0.0f;
#pragma unroll
    for (int i = 0; i < STRIPE; i++) {
        uint4 ev = *reinterpret_cast<const uint4*>(Es + i * NPTS + tid * 8);
        const __half2* hp = reinterpret_cast<const __half2*>(&ev);
        float r = rs[i];
        float2 f0 = __half22float2(hp[0]);
        float2 f1 = __half22float2(hp[1]);
        float2 f2 = __half22float2(hp[2]);
        float2 f3 = __half22float2(hp[3]);
        a[0] = fmaf(f0.x, r, a[0]); a[1] = fmaf(f0.y, r, a[1]);
        a[2] = fmaf(f1.x, r, a[2]); a[3] = fmaf(f1.y, r, a[3]);
        a[4] = fmaf(f2.x, r, a[4]); a[5] = fmaf(f2.y, r, a[5]);
        a[6] = fmaf(f3.x, r, a[6]); a[7] = fmaf(f3.y, r, a[7]);
    }
    float* cp = g_colpart + ((size_t)(b * NSTRIPES + blockIdx.x) << 12) + tid * 8;
    float4 w0 = {a[0], a[1], a[2], a[3]};
    float4 w1 = {a[4], a[5], a[6], a[7]};
    *reinterpret_cast<float4*>(cp)     = w0;
    *reinterpret_cast<float4*>(cp + 4) = w1;
}

// ---------------------------------------------------------------------------
// Finish: sum 256 stripe partials per column, update c + scalars.
// grid (16, BATCH), 256 threads.
// ---------------------------------------------------------------------------
__global__ __launch_bounds__(256) void sink_finish(int it) {
    int b = blockIdx.y, tid = threadIdx.x;
    int j = blockIdx.x * 256 + tid;
    const float* cp = g_colpart + ((size_t)b * NSTRIPES << 12) + j;
    float s = 0.0f;
#pragma unroll 8
    for (int st = 0; st < NSTRIPES; st++) s += cp[(size_t)st << 12];
    float ed = g_params[1];
    float rm = 0.5f / (ed * g_sumcA[it * BATCH + b] + g_cNa[it * BATCH + b]);
    float cj = (1.0f / 8192.0f) / (s + ed * rm);
    g_c[b * CSTRIDE + j] = cj;

    float sv = cj;
#pragma unroll
    for (int o = 16; o; o >>= 1) sv += __shfl_xor_sync(0xffffffffu, sv, o);
    __shared__ float red[8];
    if ((tid & 31) == 0) red[tid >> 5] = sv;
    __syncthreads();
    if (tid == 0) {
        float tot = 0.0f;
#pragma unroll
        for (int ww = 0; ww < 8; ww++) tot += red[ww];
        atomicAdd(&g_sumcA[(it + 1) * BATCH + b], tot);
        if (blockIdx.x == 0)
            g_cNa[(it + 1) * BATCH + b] = 0.5f / (ed * g_rsumA[it * BATCH + b] + rm);
    }
}

// ---------------------------------------------------------------------------
// Per-row stats (unchanged)
// ---------------------------------------------------------------------------
__global__ void stats_kernel() {
    int b = blockIdx.y, i = blockIdx.x, tid = threadIdx.x;
    const __half* Er = g_E + ((size_t)b << 24) + ((size_t)i << 12);
    const float* cb  = g_c + b * CSTRIDE;
    const float* pxb = g_posBx + b * NPTS;
    const float* pyb = g_posBy + b * NPTS;
    float rp = g_r[b * CSTRIDE + i];

    float sm = 0.0f, sx = 0.0f, sy = 0.0f;
    float tv[8]; int tix[8];
#pragma unroll
    for (int t = 0; t < 8; t++) { tv[t] = -1.0f; tix[t] = 0x7fffffff; }

#pragma unroll
    for (int it = 0; it < 2; ++it) {
        int j = it * 2048 + tid * 8;
        uint4 ev = *reinterpret_cast<const uint4*>(Er + j);
        const __half2* hp = reinterpret_cast<const __half2*>(&ev);
        float4 c0 = *reinterpret_cast<const float4*>(cb + j);
        float4 c1 = *reinterpret_cast<const float4*>(cb + j + 4);
        float4 x0 = *reinterpret_cast<const float4*>(pxb + j);
        float4 x1 = *reinterpret_cast<const float4*>(pxb + j + 4);
        float4 y0 = *reinterpret_cast<const float4*>(pyb + j);
        float4 y1 = *reinterpret_cast<const float4*>(pyb + j + 4);
        float2 f0 = __half22float2(hp[0]);
        float2 f1 = __half22float2(hp[1]);
        float2 f2 = __half22float2(hp[2]);
        float2 f3 = __half22float2(hp[3]);
        float ps[8] = {f0.x, f0.y, f1.x, f1.y, f2.x, f2.y, f3.x, f3.y};
        float csv[8] = {c0.x, c0.y, c0.z, c0.w, c1.x, c1.y, c1.z, c1.w};
        float xs[8] = {x0.x, x0.y, x0.z, x0.w, x1.x, x1.y, x1.z, x1.w};
        float ys[8] = {y0.x, y0.y, y0.z, y0.w, y1.x, y1.y, y1.z, y1.w};
#pragma unroll
        for (int q = 0; q < 8; q++) {
            float P  = ps[q] * rp * csv[q];
            float ot = fminf(P, 1.0f);
            sm += ot;
            sx = fmaf(ot, xs[q], sx);
            sy = fmaf(ot, ys[q], sy);
            int jj = j + q;
            if (ot > tv[7] || (ot == tv[7] && jj < tix[7])) {
                tv[7] = ot; tix[7] = jj;
#pragma unroll
                for (int q2 = 7; q2 > 0; --q2) {
                    bool sw = (tv[q2] > tv[q2 - 1]) ||
                              (tv[q2] == tv[q2 - 1] && tix[q2] < tix[q2 - 1]);
                    if (sw) {
                        float fv = tv[q2]; tv[q2] = tv[q2 - 1]; tv[q2 - 1] = fv;
                        int ii = tix[q2]; tix[q2] = tix[q2 - 1]; tix[q2 - 1] = ii;
                    }
                }
            }
        }
    }

    float s0 = sm, s1 = sx, s2 = sy;
#pragma unroll
    for (int o = 16; o; o >>= 1) {
        s0 += __shfl_xor_sync(0xffffffffu, s0, o);
        s1 += __shfl_xor_sync(0xffffffffu, s1, o);
        s2 += __shfl_xor_sync(0xffffffffu, s2, o);
    }
    __shared__ float redm[8], redx[8], redy[8];
    if ((tid & 31) == 0) { redm[tid >> 5] = s0; redx[tid >> 5] = s1; redy[tid >> 5] = s2; }

    __shared__ float sv[2048];
    __shared__ int   si[2048];
#pragma unroll
    for (int t = 0; t < 8; t++) { sv[tid * 8 + t] = tv[t]; si[tid * 8 + t] = tix[t]; }
    __syncthreads();

    for (int step = 128; step >= 1; step >>= 1) {
        if (tid < step) {
            int ia = tid * 8, ib = (tid + step) * 8;
            float av[8], bv[8], ov[8]; int ai[8], bi[8], oi[8];
#pragma unroll
            for (int t = 0; t < 8; t++) {
                av[t] = sv[ia + t]; ai[t] = si[ia + t];
                bv[t] = sv[ib + t]; bi[t] = si[ib + t];
            }
            int pa = 0, pb = 0;
#pragma unroll
            for (int o = 0; o < 8; o++) {
                bool ta = (av[pa] > bv[pb]) || (av[pa] == bv[pb] && ai[pa] <= bi[pb]);
                if (ta) { ov[o] = av[pa]; oi[o] = ai[pa]; pa++; }
                else    { ov[o] = bv[pb]; oi[o] = bi[pb]; pb++; }
            }
#pragma unroll
            for (int t = 0; t < 8; t++) { sv[ia + t] = ov[t]; si[ia + t] = oi[t]; }
        }
        __syncthreads();
    }

    if (tid == 0) {
        float smT = 0, sxT = 0, syT = 0;
#pragma unroll
        for (int w = 0; w < 8; w++) { smT += redm[w]; sxT += redx[w]; syT += redy[w]; }
        float rmass = fmaxf(smT, 1e-8f);
        float valid = fminf(fmaxf(rmass * 8192.0f, 0.0f), 1.0f);
        float top1 = sv[0], top2 = sv[1];
        float pr = fminf(fmaxf(top1 / rmass, 0.0f), 1.0f);
        float pm = fminf(fmaxf((top1 - top2) / rmass, 0.0f), 1.0f);
        float conf = fminf(fmaxf((0.6f * pr + 0.4f * pm) * valid, 0.0f), 1.0f);
        int o = b * NPTS + i;
        g_conf[o] = conf;
        g_base[o * 2]     = sxT / rmass;
        g_base[o * 2 + 1] = syT / rmass;
#pragma unroll
        for (int k = 0; k < 8; k++) {
            g_tki[o * 8 + k] = si[k];
            g_tkl[o * 8 + k] = logf(fmaxf(sv[k], 1e-38f));
        }
    }
}

// ---------------------------------------------------------------------------
// Geo validation (unchanged)
// ---------------------------------------------------------------------------
__global__ void geo_kernel(const float* __restrict__ posA) {
    int bk = blockIdx.x;
    int b = bk >> 3, k = bk & 7;
    int tid = threadIdx.x;
    __shared__ float dx[NPTS], dy[NPTS];
    for (int n = tid; n < NPTS; n += 256) {
        int idx = g_tki[(b * NPTS + n) * 8 + k];
        float ax = posA[(size_t)(b * NPTS + n) * 2];
        float ay = posA[(size_t)(b * NPTS + n) * 2 + 1];
        dx[n] = g_posBx[b * NPTS + idx] - ax;
        dy[n] = g_posBy[b * NPTS + idx] - ay;
    }
    __syncthreads();
    for (int n = tid; n < NPTS; n += 256) {
        int h = n >> 6, w = n & 63;
        int h0 = max(h - 3, 0), h1 = min(h + 3, 63);
        int w0 = max(w - 3, 0), w1 = min(w + 3, 63);
        float sxv = 0, syv = 0, sxx = 0, syy = 0;
        for (int hh = h0; hh <= h1; hh++) {
            int base = hh * 64;
            for (int ww = w0; ww <= w1; ww++) {
                float vx = dx[base + ww], vy = dy[base + ww];
                sxv += vx; syv += vy;
                sxx = fmaf(vx, vx, sxx);
                syy = fmaf(vy, vy, syy);
            }
        }
        float inv = 1.0f / (float)((h1 - h0 + 1) * (w1 - w0 + 1));
        float mx = sxv * inv, my = syv * inv;
        float vx = fmaxf(sxx * inv - mx * mx, 0.0f);
        float vy = fmaxf(syy * inv - my * my, 0.0f);
        g_geo[(b * NPTS + n) * 8 + k] = 1.0f / (1.0f + (vx + vy) * 100.0f);
    }
}

// ---------------------------------------------------------------------------
// Final blend (unchanged)
// ---------------------------------------------------------------------------
__global__ void final_kernel(float* __restrict__ out) {
    int t = blockIdx.x * 128 + threadIdx.x;
    int b = t >> 12, n = t & 4095;
    int o = b * NPTS + n;
    float gwv = g_params[2];
    float lc[8]; int id[8];
    float m = -1e30f;
#pragma unroll
    for (int k = 0; k < 8; k++) {
        lc[k] = g_tkl[o * 8 + k] + gwv * g_geo[o * 8 + k];
        id[k] = g_tki[o * 8 + k];
        m = fmaxf(m, lc[k]);
    }
    float ws = 0, rx = 0, ry = 0;
#pragma unroll
    for (int k = 0; k < 8; k++) {
        float w = fexpf(fmaxf(lc[k] - m, -80.0f));
        ws += w;
        rx = fmaf(w, g_posBx[b * NPTS + id[k]], rx);
        ry = fmaf(w, g_posBy[b * NPTS + id[k]], ry);
    }
    rx /= ws; ry /= ws;
    float conf = g_conf[o];
    out[o * 2]     = conf * rx + (1.0f - conf) * g_base[o * 2];
    out[o * 2 + 1] = conf * ry + (1.0f - conf) * g_base[o * 2 + 1];
}

// ---------------------------------------------------------------------------
extern "C" void kernel_launch(void* const* d_in, const int* in_sizes, int n_in,
                              void* d_out, int out_size) {
    const float* fA   = (const float*)d_in[0];
    const float* fB   = (const float*)d_in[1];
    const float* pA   = (const float*)d_in[2];
    const float* pB   = (const float*)d_in[3];
    const float* dust = (const float*)d_in[4];
    const float* geow = (const float*)d_in[5];
    const float* temp = (const float*)d_in[6];
    float* out = (float*)d_out;

    const int SK_SMEM = NPTS * 4 + STRIPE * NPTS * 2;   // 147456 B
    cudaFuncSetAttribute(sink_stripe, cudaFuncAttributeMaxDynamicSharedMemorySize, SK_SMEM);

    prep_kernel<<<33, 256>>>(dust, geow, temp, pB);
    norm_kernel<<<2048, 256>>>(fA, fB);
    gemm_exp_kernel<<<dim3(32, 32, BATCH), 256>>>();
    for (int it = 0; it < ITERS; ++it) {
        sink_stripe<<<dim3(NSTRIPES, BATCH), 512, SK_SMEM>>>(it);
        sink_finish<<<dim3(16, BATCH), 256>>>(it);
    }
    stats_kernel<<<dim3(NPTS, BATCH), 256>>>();
    geo_kernel<<<BATCH * TOPK, 256>>>(pA);
    final_kernel<<<64, 128>>>(out);
}

// round 6
// speedup vs baseline: 1.4001x; 1.1446x over previous
#include <cuda_runtime.h>
#include <cuda_fp16.h>
#include <cstdint>
#include <math.h>

#define BATCH 2
#define NPTS  4096
#define CDIM  128
#define TOPK  8
#define ITERS 15
#define CSTRIDE 4112
#define STRIPE 8
#define NSTRIPES (NPTS / STRIPE)     // 512
#define NGROUPS 16                   // finish level-1 groups (32 stripes each)

// ---------------------------------------------------------------------------
// Device scratch
// ---------------------------------------------------------------------------
__device__ __half g_E[(size_t)BATCH * NPTS * NPTS];   // exp(scores), 67 MB
__device__ __half g_hA[BATCH * NPTS * CDIM];
__device__ __half g_hB[BATCH * NPTS * CDIM];
__device__ float  g_r[BATCH * CSTRIDE];
__device__ float  g_c[BATCH * CSTRIDE];
__device__ float  g_colpart[(size_t)BATCH * NSTRIPES * NPTS];   // 16 MB
__device__ float  g_colpart2[BATCH * NGROUPS * NPTS];           // 512 KB
__device__ float  g_rsumA[ITERS * BATCH];
__device__ float  g_sumcA[(ITERS + 1) * BATCH];
__device__ float  g_cNa[(ITERS + 1) * BATCH];
__device__ float  g_posBx[BATCH * NPTS];
__device__ float  g_posBy[BATCH * NPTS];
__device__ float  g_conf[BATCH * NPTS];
__device__ float  g_base[BATCH * NPTS * 2];
__device__ int    g_tki[BATCH * NPTS * TOPK];
__device__ float  g_tkl[BATCH * NPTS * TOPK];
__device__ float  g_geo[BATCH * NPTS * TOPK];
__device__ float  g_params[4];

// ---------------------------------------------------------------------------
// FMA-pipe exp (no MUFU)
// ---------------------------------------------------------------------------
__device__ __forceinline__ float fexpf(float x) {
    float t = x * 1.4426950408889634f;
    float z = t + 12582912.0f;
    int   ni = __float_as_int(z);
    float n  = z - 12582912.0f;
    float f  = t - n;
    float p = 1.5403530e-4f;
    p = fmaf(p, f, 1.33335581e-3f);
    p = fmaf(p, f, 9.61812911e-3f);
    p = fmaf(p, f, 5.55041087e-2f);
    p = fmaf(p, f, 2.40226507e-1f);
    p = fmaf(p, f, 6.93147181e-1f);
    p = fmaf(p, f, 1.0f);
    int e = (ni & 0x7FFFFF) - 0x400000;
    float s = __int_as_float((e + 127) << 23);
    return p * s;
}

// ---------------------------------------------------------------------------
// Prep
// ---------------------------------------------------------------------------
__global__ void prep_kernel(const float* __restrict__ dust,
                            const float* __restrict__ geow,
                            const float* __restrict__ temp,
                            const float* __restrict__ posB) {
    int t = blockIdx.x * 256 + threadIdx.x;
    if (t == 0) {
        float tr = temp[0];
        g_params[0] = 1.0f / tr;
        float tc = fminf(fmaxf(tr, 0.2f), 10.0f);
        float ds = fminf(fmaxf(dust[0] / tc, -50.0f), 50.0f);
        g_params[1] = expf(ds);
        g_params[2] = fminf(fmaxf(geow[0], 0.0f), 2.0f);
    }
    if (t < BATCH * CSTRIDE) g_c[t] = 1.0f;
    if (t < BATCH * NPTS) {
        g_posBx[t] = posB[2 * t];
        g_posBy[t] = posB[2 * t + 1];
    }
    if (t < ITERS * BATCH) g_rsumA[t] = 0.0f;
    if (t < (ITERS + 1) * BATCH) {
        g_sumcA[t] = (t < BATCH) ? 4096.0f : 0.0f;
        g_cNa[t]   = (t < BATCH) ? 1.0f    : 0.0f;
    }
}

// ---------------------------------------------------------------------------
// L2-normalize -> fp16 features
// ---------------------------------------------------------------------------
__global__ void norm_kernel(const float* __restrict__ fA, const float* __restrict__ fB) {
    int wg   = blockIdx.x * 8 + (threadIdx.x >> 5);
    int lane = threadIdx.x & 31;
    int tensor = wg >> 13;
    int row    = wg & 8191;
    const float* src = tensor ? fB : fA;
    __half*      dst = tensor ? g_hB : g_hA;
    float4 v = *reinterpret_cast<const float4*>(src + (size_t)row * CDIM + lane * 4);
    float ss = v.x * v.x + v.y * v.y + v.z * v.z + v.w * v.w;
#pragma unroll
    for (int o = 16; o; o >>= 1) ss += __shfl_xor_sync(0xffffffffu, ss, o);
    float inv = 1.0f / fmaxf(sqrtf(ss), 1e-12f);
    __half2 h01 = __floats2half2_rn(v.x * inv, v.y * inv);
    __half2 h23 = __floats2half2_rn(v.z * inv, v.w * inv);
    uint2 u;
    u.x = *reinterpret_cast<uint32_t*>(&h01);
    u.y = *reinterpret_cast<uint32_t*>(&h23);
    *reinterpret_cast<uint2*>(dst + (size_t)row * CDIM + lane * 4) = u;
}

// ---------------------------------------------------------------------------
// Tensor-core GEMM + exp epilogue (unchanged)
// ---------------------------------------------------------------------------
__device__ __forceinline__ void ldsm4(uint32_t* r, uint32_t addr) {
    asm volatile("ldmatrix.sync.aligned.m8n8.x4.shared.b16 {%0,%1,%2,%3}, [%4];\n"
        : "=r"(r[0]), "=r"(r[1]), "=r"(r[2]), "=r"(r[3]) : "r"(addr));
}
__device__ __forceinline__ void mma16816(float* c, const uint32_t* a, const uint32_t* b) {
    asm volatile("mma.sync.aligned.m16n8k16.row.col.f32.f16.f16.f32 "
        "{%0,%1,%2,%3}, {%4,%5,%6,%7}, {%8,%9}, {%0,%1,%2,%3};\n"
        : "+f"(c[0]), "+f"(c[1]), "+f"(c[2]), "+f"(c[3])
        : "r"(a[0]), "r"(a[1]), "r"(a[2]), "r"(a[3]), "r"(b[0]), "r"(b[1]));
}

#define SMK 72
#define SOUTS 136

__global__ __launch_bounds__(256) void gemm_exp_kernel() {
    int b  = blockIdx.z;
    int i0 = blockIdx.y * 128;
    int j0 = blockIdx.x * 128;
    const __half* A  = g_hA + (size_t)b * NPTS * CDIM;
    const __half* Bm = g_hB + (size_t)b * NPTS * CDIM;

    __shared__ __align__(16) __half smem[2 * 128 * SMK];
    __half* sA = smem;
    __half* sB = smem + 128 * SMK;

    int tid = threadIdx.x;
    int w = tid >> 5, lane = tid & 31;
    int wm = (w >> 1) * 32, wn = (w & 1) * 64;
    float itp = g_params[0];

    float acc[2][8][4];
#pragma unroll
    for (int mt = 0; mt < 2; mt++)
#pragma unroll
        for (int nt = 0; nt < 8; nt++)
#pragma unroll
            for (int q = 0; q < 4; q++) acc[mt][nt][q] = 0.0f;

#pragma unroll
    for (int kb = 0; kb < CDIM; kb += 64) {
        if (kb) __syncthreads();
#pragma unroll
        for (int e = 0; e < 4; e++) {
            int idx = tid + e * 256;
            int r = idx >> 3, c8 = idx & 7;
            *reinterpret_cast<uint4*>(sA + r * SMK + c8 * 8) =
                *reinterpret_cast<const uint4*>(A + (size_t)(i0 + r) * CDIM + kb + c8 * 8);
            *reinterpret_cast<uint4*>(sB + r * SMK + c8 * 8) =
                *reinterpret_cast<const uint4*>(Bm + (size_t)(j0 + r) * CDIM + kb + c8 * 8);
        }
        __syncthreads();

#pragma unroll
        for (int ks = 0; ks < 4; ks++) {
            int k0 = ks * 16;
            uint32_t afr[2][4];
#pragma unroll
            for (int mt = 0; mt < 2; mt++) {
                int row = wm + mt * 16 + (lane & 15);
                int col = k0 + ((lane >> 4) << 3);
                uint32_t addr = (uint32_t)__cvta_generic_to_shared(sA + row * SMK + col);
                ldsm4(afr[mt], addr);
            }
            uint32_t bfr[8][2];
#pragma unroll
            for (int p = 0; p < 4; p++) {
                int l4 = lane & 7, g = lane >> 3;
                int row = wn + p * 16 + ((g >> 1) << 3) + l4;
                int col = k0 + ((g & 1) << 3);
                uint32_t addr = (uint32_t)__cvta_generic_to_shared(sB + row * SMK + col);
                uint32_t t4[4];
                ldsm4(t4, addr);
                bfr[2 * p][0] = t4[0]; bfr[2 * p][1] = t4[1];
                bfr[2 * p + 1][0] = t4[2]; bfr[2 * p + 1][1] = t4[3];
            }
#pragma unroll
            for (int mt = 0; mt < 2; mt++)
#pragma unroll
                for (int nt = 0; nt < 8; nt++)
                    mma16816(acc[mt][nt], afr[mt], bfr[nt]);
        }
    }
    __syncthreads();

    __half* sO = smem;
#pragma unroll
    for (int mt = 0; mt < 2; mt++) {
#pragma unroll
        for (int nt = 0; nt < 8; nt++) {
            float e0 = fexpf(fminf(fmaxf(acc[mt][nt][0] * itp, -50.0f), 50.0f));
            float e1 = fexpf(fminf(fmaxf(acc[mt][nt][1] * itp, -50.0f), 50.0f));
            float e2 = fexpf(fminf(fmaxf(acc[mt][nt][2] * itp, -50.0f), 50.0f));
            float e3 = fexpf(fminf(fmaxf(acc[mt][nt][3] * itp, -50.0f), 50.0f));
            int row  = wm + mt * 16 + (lane >> 2);
            int colh = wn + nt * 8 + ((lane & 3) << 1);
            *reinterpret_cast<__half2*>(sO + row * SOUTS + colh)       = __floats2half2_rn(e0, e1);
            *reinterpret_cast<__half2*>(sO + (row + 8) * SOUTS + colh) = __floats2half2_rn(e2, e3);
        }
    }
    __syncthreads();

    __half* Eb = g_E + ((size_t)b << 24);
#pragma unroll
    for (int e = 0; e < 8; e++) {
        int idx = tid + e * 256;
        int r = idx >> 4, c = idx & 15;
        *reinterpret_cast<uint4*>(Eb + (size_t)(i0 + r) * NPTS + j0 + c * 8) =
            *reinterpret_cast<uint4*>(sO + r * SOUTS + c * 8);
    }
}

// ---------------------------------------------------------------------------
// Sinkhorn stripe kernel: 8 rows x 4096 cols staged in smem.
// 512 threads (2 warps per row), 80 KB dynamic smem -> 2 blocks/SM.
// grid (512, BATCH).
// ---------------------------------------------------------------------------
extern __shared__ __align__(16) unsigned char sk_smem[];

__global__ __launch_bounds__(512) void sink_stripe(int it) {
    int b = blockIdx.y;
    int i0 = blockIdx.x * STRIPE;
    int tid = threadIdx.x, w = tid >> 5, lane = tid & 31;
    float*  cs = reinterpret_cast<float*>(sk_smem);               // 16388 B
    __half* Es = reinterpret_cast<__half*>(sk_smem + 16400);      // 64 KB
    __shared__ float rs[STRIPE];
    __shared__ float psum[16];

    const float* cg = g_c + b * CSTRIDE;
#pragma unroll
    for (int q = 0; q < 8; q++) cs[tid + q * 512] = cg[tid + q * 512];
    if (tid == 0) cs[4096] = cg[4096];
    __syncthreads();

    float ed = g_params[1];
    float cN = g_cNa[it * BATCH + b];

    // phase 1: warp pair (2w, 2w+1) owns row lr = w>>1; halves of the row.
    int lr = w >> 1, h = w & 1;
    const __half* Er = g_E + ((size_t)b << 24) + ((size_t)(i0 + lr) << 12);
    __half* Esr = Es + lr * NPTS;
    float sum = 0.0f;
#pragma unroll
    for (int ch = 8 * h; ch < 8 * h + 8; ch++) {
        int j = ch * 256 + lane * 8;
        uint4 ev = *reinterpret_cast<const uint4*>(Er + j);
        *reinterpret_cast<uint4*>(Esr + j) = ev;
        const __half2* hp = reinterpret_cast<const __half2*>(&ev);
        float4 c0 = *reinterpret_cast<const float4*>(cs + j);
        float4 c1 = *reinterpret_cast<const float4*>(cs + j + 4);
        float2 f0 = __half22float2(hp[0]);
        float2 f1 = __half22float2(hp[1]);
        float2 f2 = __half22float2(hp[2]);
        float2 f3 = __half22float2(hp[3]);
        sum = fmaf(f0.x, c0.x, sum); sum = fmaf(f0.y, c0.y, sum);
        sum = fmaf(f1.x, c0.z, sum); sum = fmaf(f1.y, c0.w, sum);
        sum = fmaf(f2.x, c1.x, sum); sum = fmaf(f2.y, c1.y, sum);
        sum = fmaf(f3.x, c1.z, sum); sum = fmaf(f3.y, c1.w, sum);
    }
#pragma unroll
    for (int o = 16; o; o >>= 1) sum += __shfl_xor_sync(0xffffffffu, sum, o);
    if (lane == 0) psum[w] = sum;
    __syncthreads();

    if (tid < STRIPE) {
        float tot = psum[2 * tid] + psum[2 * tid + 1];
        float r = (1.0f / 8192.0f) / (tot + ed * cN);
        rs[tid] = r;
        g_r[b * CSTRIDE + i0 + tid] = r;
        float v = r;
#pragma unroll
        for (int o = 4; o; o >>= 1) v += __shfl_xor_sync(0xffu, v, o);
        if (tid == 0) atomicAdd(&g_rsumA[it * BATCH + b], v);
    }
    __syncthreads();

    // phase 2: thread owns 8 cols (tid*8), accumulate over 8 smem rows
    float a[8];
#pragma unroll
    for (int q = 0; q < 8; q++) a[q] = 0.0f;
#pragma unroll
    for (int i = 0; i < STRIPE; i++) {
        uint4 ev = *reinterpret_cast<const uint4*>(Es + i * NPTS + tid * 8);
        const __half2* hp = reinterpret_cast<const __half2*>(&ev);
        float r = rs[i];
        float2 f0 = __half22float2(hp[0]);
        float2 f1 = __half22float2(hp[1]);
        float2 f2 = __half22float2(hp[2]);
        float2 f3 = __half22float2(hp[3]);
        a[0] = fmaf(f0.x, r, a[0]); a[1] = fmaf(f0.y, r, a[1]);
        a[2] = fmaf(f1.x, r, a[2]); a[3] = fmaf(f1.y, r, a[3]);
        a[4] = fmaf(f2.x, r, a[4]); a[5] = fmaf(f2.y, r, a[5]);
        a[6] = fmaf(f3.x, r, a[6]); a[7] = fmaf(f3.y, r, a[7]);
    }
    float* cp = g_colpart + (((size_t)b * NSTRIPES + blockIdx.x) << 12) + tid * 8;
    float4 w0 = {a[0], a[1], a[2], a[3]};
    float4 w1 = {a[4], a[5], a[6], a[7]};
    *reinterpret_cast<float4*>(cp)     = w0;
    *reinterpret_cast<float4*>(cp + 4) = w1;
}

// ---------------------------------------------------------------------------
// Finish level 1: sum 32 stripe partials per column per group.
// grid (16 colblocks * 16 groups, BATCH), 256 threads.
// ---------------------------------------------------------------------------
__global__ __launch_bounds__(256) void sink_finish1() {
    int b  = blockIdx.y;
    int cb = blockIdx.x & 15;
    int sg = blockIdx.x >> 4;
    int col = cb * 256 + threadIdx.x;
    const float* cp = g_colpart + (((size_t)b * NSTRIPES + sg * 32) << 12) + col;
    float s = 0.0f;
#pragma unroll 8
    for (int st = 0; st < 32; st++) s += cp[(size_t)st << 12];
    g_colpart2[(b * NGROUPS + sg) * NPTS + col] = s;
}

// ---------------------------------------------------------------------------
// Finish level 2: sum 16 group partials, update c + scalars.
// grid (16, BATCH), 256 threads.
// ---------------------------------------------------------------------------
__global__ __launch_bounds__(256) void sink_finish2(int it) {
    int b = blockIdx.y, tid = threadIdx.x;
    int j = blockIdx.x * 256 + tid;
    const float* cp = g_colpart2 + b * NGROUPS * NPTS + j;
    float s = 0.0f;
#pragma unroll
    for (int sg = 0; sg < NGROUPS; sg++) s += cp[sg * NPTS];
    float ed = g_params[1];
    float rm = 0.5f / (ed * g_sumcA[it * BATCH + b] + g_cNa[it * BATCH + b]);
    float cj = (1.0f / 8192.0f) / (s + ed * rm);
    g_c[b * CSTRIDE + j] = cj;

    float sv = cj;
#pragma unroll
    for (int o = 16; o; o >>= 1) sv += __shfl_xor_sync(0xffffffffu, sv, o);
    __shared__ float red[8];
    if ((tid & 31) == 0) red[tid >> 5] = sv;
    __syncthreads();
    if (tid == 0) {
        float tot = 0.0f;
#pragma unroll
        for (int ww = 0; ww < 8; ww++) tot += red[ww];
        atomicAdd(&g_sumcA[(it + 1) * BATCH + b], tot);
        if (blockIdx.x == 0)
            g_cNa[(it + 1) * BATCH + b] = 0.5f / (ed * g_rsumA[it * BATCH + b] + rm);
    }
}

// ---------------------------------------------------------------------------
// Per-row stats (unchanged)
// ---------------------------------------------------------------------------
__global__ void stats_kernel() {
    int b = blockIdx.y, i = blockIdx.x, tid = threadIdx.x;
    const __half* Er = g_E + ((size_t)b << 24) + ((size_t)i << 12);
    const float* cb  = g_c + b * CSTRIDE;
    const float* pxb = g_posBx + b * NPTS;
    const float* pyb = g_posBy + b * NPTS;
    float rp = g_r[b * CSTRIDE + i];

    float sm = 0.0f, sx = 0.0f, sy = 0.0f;
    float tv[8]; int tix[8];
#pragma unroll
    for (int t = 0; t < 8; t++) { tv[t] = -1.0f; tix[t] = 0x7fffffff; }

#pragma unroll
    for (int it = 0; it < 2; ++it) {
        int j = it * 2048 + tid * 8;
        uint4 ev = *reinterpret_cast<const uint4*>(Er + j);
        const __half2* hp = reinterpret_cast<const __half2*>(&ev);
        float4 c0 = *reinterpret_cast<const float4*>(cb + j);
        float4 c1 = *reinterpret_cast<const float4*>(cb + j + 4);
        float4 x0 = *reinterpret_cast<const float4*>(pxb + j);
        float4 x1 = *reinterpret_cast<const float4*>(pxb + j + 4);
        float4 y0 = *reinterpret_cast<const float4*>(pyb + j);
        float4 y1 = *reinterpret_cast<const float4*>(pyb + j + 4);
        float2 f0 = __half22float2(hp[0]);
        float2 f1 = __half22float2(hp[1]);
        float2 f2 = __half22float2(hp[2]);
        float2 f3 = __half22float2(hp[3]);
        float ps[8] = {f0.x, f0.y, f1.x, f1.y, f2.x, f2.y, f3.x, f3.y};
        float csv[8] = {c0.x, c0.y, c0.z, c0.w, c1.x, c1.y, c1.z, c1.w};
        float xs[8] = {x0.x, x0.y, x0.z, x0.w, x1.x, x1.y, x1.z, x1.w};
        float ys[8] = {y0.x, y0.y, y0.z, y0.w, y1.x, y1.y, y1.z, y1.w};
#pragma unroll
        for (int q = 0; q < 8; q++) {
            float P  = ps[q] * rp * csv[q];
            float ot = fminf(P, 1.0f);
            sm += ot;
            sx = fmaf(ot, xs[q], sx);
            sy = fmaf(ot, ys[q], sy);
            int jj = j + q;
            if (ot > tv[7] || (ot == tv[7] && jj < tix[7])) {
                tv[7] = ot; tix[7] = jj;
#pragma unroll
                for (int q2 = 7; q2 > 0; --q2) {
                    bool sw = (tv[q2] > tv[q2 - 1]) ||
                              (tv[q2] == tv[q2 - 1] && tix[q2] < tix[q2 - 1]);
                    if (sw) {
                        float fv = tv[q2]; tv[q2] = tv[q2 - 1]; tv[q2 - 1] = fv;
                        int ii = tix[q2]; tix[q2] = tix[q2 - 1]; tix[q2 - 1] = ii;
                    }
                }
            }
        }
    }

    float s0 = sm, s1 = sx, s2 = sy;
#pragma unroll
    for (int o = 16; o; o >>= 1) {
        s0 += __shfl_xor_sync(0xffffffffu, s0, o);
        s1 += __shfl_xor_sync(0xffffffffu, s1, o);
        s2 += __shfl_xor_sync(0xffffffffu, s2, o);
    }
    __shared__ float redm[8], redx[8], redy[8];
    if ((tid & 31) == 0) { redm[tid >> 5] = s0; redx[tid >> 5] = s1; redy[tid >> 5] = s2; }

    __shared__ float sv[2048];
    __shared__ int   si[2048];
#pragma unroll
    for (int t = 0; t < 8; t++) { sv[tid * 8 + t] = tv[t]; si[tid * 8 + t] = tix[t]; }
    __syncthreads();

    for (int step = 128; step >= 1; step >>= 1) {
        if (tid < step) {
            int ia = tid * 8, ib = (tid + step) * 8;
            float av[8], bv[8], ov[8]; int ai[8], bi[8], oi[8];
#pragma unroll
            for (int t = 0; t < 8; t++) {
                av[t] = sv[ia + t]; ai[t] = si[ia + t];
                bv[t] = sv[ib + t]; bi[t] = si[ib + t];
            }
            int pa = 0, pb = 0;
#pragma unroll
            for (int o = 0; o < 8; o++) {
                bool ta = (av[pa] > bv[pb]) || (av[pa] == bv[pb] && ai[pa] <= bi[pb]);
                if (ta) { ov[o] = av[pa]; oi[o] = ai[pa]; pa++; }
                else    { ov[o] = bv[pb]; oi[o] = bi[pb]; pb++; }
            }
#pragma unroll
            for (int t = 0; t < 8; t++) { sv[ia + t] = ov[t]; si[ia + t] = oi[t]; }
        }
        __syncthreads();
    }

    if (tid == 0) {
        float smT = 0, sxT = 0, syT = 0;
#pragma unroll
        for (int w = 0; w < 8; w++) { smT += redm[w]; sxT += redx[w]; syT += redy[w]; }
        float rmass = fmaxf(smT, 1e-8f);
        float valid = fminf(fmaxf(rmass * 8192.0f, 0.0f), 1.0f);
        float top1 = sv[0], top2 = sv[1];
        float pr = fminf(fmaxf(top1 / rmass, 0.0f), 1.0f);
        float pm = fminf(fmaxf((top1 - top2) / rmass, 0.0f), 1.0f);
        float conf = fminf(fmaxf((0.6f * pr + 0.4f * pm) * valid, 0.0f), 1.0f);
        int o = b * NPTS + i;
        g_conf[o] = conf;
        g_base[o * 2]     = sxT / rmass;
        g_base[o * 2 + 1] = syT / rmass;
#pragma unroll
        for (int k = 0; k < 8; k++) {
            g_tki[o * 8 + k] = si[k];
            g_tkl[o * 8 + k] = logf(fmaxf(sv[k], 1e-38f));
        }
    }
}

// ---------------------------------------------------------------------------
// Geo validation (unchanged)
// ---------------------------------------------------------------------------
__global__ void geo_kernel(const float* __restrict__ posA) {
    int bk = blockIdx.x;
    int b = bk >> 3, k = bk & 7;
    int tid = threadIdx.x;
    __shared__ float dx[NPTS], dy[NPTS];
    for (int n = tid; n < NPTS; n += 256) {
        int idx = g_tki[(b * NPTS + n) * 8 + k];
        float ax = posA[(size_t)(b * NPTS + n) * 2];
        float ay = posA[(size_t)(b * NPTS + n) * 2 + 1];
        dx[n] = g_posBx[b * NPTS + idx] - ax;
        dy[n] = g_posBy[b * NPTS + idx] - ay;
    }
    __syncthreads();
    for (int n = tid; n < NPTS; n += 256) {
        int h = n >> 6, w = n & 63;
        int h0 = max(h - 3, 0), h1 = min(h + 3, 63);
        int w0 = max(w - 3, 0), w1 = min(w + 3, 63);
        float sxv = 0, syv = 0, sxx = 0, syy = 0;
        for (int hh = h0; hh <= h1; hh++) {
            int base = hh * 64;
            for (int ww = w0; ww <= w1; ww++) {
                float vx = dx[base + ww], vy = dy[base + ww];
                sxv += vx; syv += vy;
                sxx = fmaf(vx, vx, sxx);
                syy = fmaf(vy, vy, syy);
            }
        }
        float inv = 1.0f / (float)((h1 - h0 + 1) * (w1 - w0 + 1));
        float mx = sxv * inv, my = syv * inv;
        float vx = fmaxf(sxx * inv - mx * mx, 0.0f);
        float vy = fmaxf(syy * inv - my * my, 0.0f);
        g_geo[(b * NPTS + n) * 8 + k] = 1.0f / (1.0f + (vx + vy) * 100.0f);
    }
}

// ---------------------------------------------------------------------------
// Final blend (unchanged)
// ---------------------------------------------------------------------------
__global__ void final_kernel(float* __restrict__ out) {
    int t = blockIdx.x * 128 + threadIdx.x;
    int b = t >> 12, n = t & 4095;
    int o = b * NPTS + n;
    float gwv = g_params[2];
    float lc[8]; int id[8];
    float m = -1e30f;
#pragma unroll
    for (int k = 0; k < 8; k++) {
        lc[k] = g_tkl[o * 8 + k] + gwv * g_geo[o * 8 + k];
        id[k] = g_tki[o * 8 + k];
        m = fmaxf(m, lc[k]);
    }
    float ws = 0, rx = 0, ry = 0;
#pragma unroll
    for (int k = 0; k < 8; k++) {
        float w = fexpf(fmaxf(lc[k] - m, -80.0f));
        ws += w;
        rx = fmaf(w, g_posBx[b * NPTS + id[k]], rx);
        ry = fmaf(w, g_posBy[b * NPTS + id[k]], ry);
    }
    rx /= ws; ry /= ws;
    float conf = g_conf[o];
    out[o * 2]     = conf * rx + (1.0f - conf) * g_base[o * 2];
    out[o * 2 + 1] = conf * ry + (1.0f - conf) * g_base[o * 2 + 1];
}

// ---------------------------------------------------------------------------
extern "C" void kernel_launch(void* const* d_in, const int* in_sizes, int n_in,
                              void* d_out, int out_size) {
    const float* fA   = (const float*)d_in[0];
    const float* fB   = (const float*)d_in[1];
    const float* pA   = (const float*)d_in[2];
    const float* pB   = (const float*)d_in[3];
    const float* dust = (const float*)d_in[4];
    const float* geow = (const float*)d_in[5];
    const float* temp = (const float*)d_in[6];
    float* out = (float*)d_out;

    const int SK_SMEM = 16400 + STRIPE * NPTS * 2;   // 81936 B
    cudaFuncSetAttribute(sink_stripe, cudaFuncAttributeMaxDynamicSharedMemorySize, SK_SMEM);

    prep_kernel<<<33, 256>>>(dust, geow, temp, pB);
    norm_kernel<<<2048, 256>>>(fA, fB);
    gemm_exp_kernel<<<dim3(32, 32, BATCH), 256>>>();
    for (int it = 0; it < ITERS; ++it) {
        sink_stripe<<<dim3(NSTRIPES, BATCH), 512, SK_SMEM>>>(it);
        sink_finish1<<<dim3(256, BATCH), 256>>>();
        sink_finish2<<<dim3(16, BATCH), 256>>>(it);
    }
    stats_kernel<<<dim3(NPTS, BATCH), 256>>>();
    geo_kernel<<<BATCH * TOPK, 256>>>(pA);
    final_kernel<<<64, 128>>>(out);
}

// round 7
// speedup vs baseline: 1.7501x; 1.2500x over previous
#include <cuda_runtime.h>
#include <cuda_fp16.h>
#include <cstdint>
#include <math.h>

#define BATCH 2
#define NPTS  4096
#define CDIM  128
#define TOPK  8
#define ITERS 15
#define CSTRIDE 4112
#define STRIPE 16
#define NSTRIPES (NPTS / STRIPE)     // 256

// ---------------------------------------------------------------------------
// Device scratch
// ---------------------------------------------------------------------------
__device__ __half g_E[(size_t)BATCH * NPTS * NPTS];   // exp(scores), 67 MB
__device__ __half g_hA[BATCH * NPTS * CDIM];
__device__ __half g_hB[BATCH * NPTS * CDIM];
__device__ float  g_r[BATCH * CSTRIDE];
__device__ float  g_c[BATCH * CSTRIDE];
__device__ float  g_colpart[(size_t)BATCH * NSTRIPES * NPTS];   // 8 MB
__device__ float  g_rsumA[ITERS * BATCH];
__device__ float  g_sumcA[(ITERS + 1) * BATCH];
__device__ float  g_cNa[(ITERS + 1) * BATCH];
__device__ float  g_posBx[BATCH * NPTS];
__device__ float  g_posBy[BATCH * NPTS];
__device__ float  g_conf[BATCH * NPTS];
__device__ float  g_base[BATCH * NPTS * 2];
__device__ int    g_tki[BATCH * NPTS * TOPK];
__device__ float  g_tkl[BATCH * NPTS * TOPK];
__device__ float  g_geo[BATCH * NPTS * TOPK];
__device__ float  g_params[4];

// ---------------------------------------------------------------------------
// FMA-pipe exp (no MUFU)
// ---------------------------------------------------------------------------
__device__ __forceinline__ float fexpf(float x) {
    float t = x * 1.4426950408889634f;
    float z = t + 12582912.0f;
    int   ni = __float_as_int(z);
    float n  = z - 12582912.0f;
    float f  = t - n;
    float p = 1.5403530e-4f;
    p = fmaf(p, f, 1.33335581e-3f);
    p = fmaf(p, f, 9.61812911e-3f);
    p = fmaf(p, f, 5.55041087e-2f);
    p = fmaf(p, f, 2.40226507e-1f);
    p = fmaf(p, f, 6.93147181e-1f);
    p = fmaf(p, f, 1.0f);
    int e = (ni & 0x7FFFFF) - 0x400000;
    float s = __int_as_float((e + 127) << 23);
    return p * s;
}

// ---------------------------------------------------------------------------
// Prep
// ---------------------------------------------------------------------------
__global__ void prep_kernel(const float* __restrict__ dust,
                            const float* __restrict__ geow,
                            const float* __restrict__ temp,
                            const float* __restrict__ posB) {
    int t = blockIdx.x * 256 + threadIdx.x;
    if (t == 0) {
        float tr = temp[0];
        g_params[0] = 1.0f / tr;
        float tc = fminf(fmaxf(tr, 0.2f), 10.0f);
        float ds = fminf(fmaxf(dust[0] / tc, -50.0f), 50.0f);
        g_params[1] = expf(ds);
        g_params[2] = fminf(fmaxf(geow[0], 0.0f), 2.0f);
    }
    if (t < BATCH * CSTRIDE) g_c[t] = 1.0f;
    if (t < BATCH * NPTS) {
        g_posBx[t] = posB[2 * t];
        g_posBy[t] = posB[2 * t + 1];
    }
    if (t < ITERS * BATCH) g_rsumA[t] = 0.0f;
    if (t < (ITERS + 1) * BATCH) {
        g_sumcA[t] = (t < BATCH) ? 4096.0f : 0.0f;
        g_cNa[t]   = (t < BATCH) ? 1.0f    : 0.0f;
    }
}

// ---------------------------------------------------------------------------
// L2-normalize -> fp16 features
// ---------------------------------------------------------------------------
__global__ void norm_kernel(const float* __restrict__ fA, const float* __restrict__ fB) {
    int wg   = blockIdx.x * 8 + (threadIdx.x >> 5);
    int lane = threadIdx.x & 31;
    int tensor = wg >> 13;
    int row    = wg & 8191;
    const float* src = tensor ? fB : fA;
    __half*      dst = tensor ? g_hB : g_hA;
    float4 v = *reinterpret_cast<const float4*>(src + (size_t)row * CDIM + lane * 4);
    float ss = v.x * v.x + v.y * v.y + v.z * v.z + v.w * v.w;
#pragma unroll
    for (int o = 16; o; o >>= 1) ss += __shfl_xor_sync(0xffffffffu, ss, o);
    float inv = 1.0f / fmaxf(sqrtf(ss), 1e-12f);
    __half2 h01 = __floats2half2_rn(v.x * inv, v.y * inv);
    __half2 h23 = __floats2half2_rn(v.z * inv, v.w * inv);
    uint2 u;
    u.x = *reinterpret_cast<uint32_t*>(&h01);
    u.y = *reinterpret_cast<uint32_t*>(&h23);
    *reinterpret_cast<uint2*>(dst + (size_t)row * CDIM + lane * 4) = u;
}

// ---------------------------------------------------------------------------
// Tensor-core GEMM + exp epilogue (unchanged)
// ---------------------------------------------------------------------------
__device__ __forceinline__ void ldsm4(uint32_t* r, uint32_t addr) {
    asm volatile("ldmatrix.sync.aligned.m8n8.x4.shared.b16 {%0,%1,%2,%3}, [%4];\n"
        : "=r"(r[0]), "=r"(r[1]), "=r"(r[2]), "=r"(r[3]) : "r"(addr));
}
__device__ __forceinline__ void mma16816(float* c, const uint32_t* a, const uint32_t* b) {
    asm volatile("mma.sync.aligned.m16n8k16.row.col.f32.f16.f16.f32 "
        "{%0,%1,%2,%3}, {%4,%5,%6,%7}, {%8,%9}, {%0,%1,%2,%3};\n"
        : "+f"(c[0]), "+f"(c[1]), "+f"(c[2]), "+f"(c[3])
        : "r"(a[0]), "r"(a[1]), "r"(a[2]), "r"(a[3]), "r"(b[0]), "r"(b[1]));
}

#define SMK 72
#define SOUTS 136

__global__ __launch_bounds__(256) void gemm_exp_kernel() {
    int b  = blockIdx.z;
    int i0 = blockIdx.y * 128;
    int j0 = blockIdx.x * 128;
    const __half* A  = g_hA + (size_t)b * NPTS * CDIM;
    const __half* Bm = g_hB + (size_t)b * NPTS * CDIM;

    __shared__ __align__(16) __half smem[2 * 128 * SMK];
    __half* sA = smem;
    __half* sB = smem + 128 * SMK;

    int tid = threadIdx.x;
    int w = tid >> 5, lane = tid & 31;
    int wm = (w >> 1) * 32, wn = (w & 1) * 64;
    float itp = g_params[0];

    float acc[2][8][4];
#pragma unroll
    for (int mt = 0; mt < 2; mt++)
#pragma unroll
        for (int nt = 0; nt < 8; nt++)
#pragma unroll
            for (int q = 0; q < 4; q++) acc[mt][nt][q] = 0.0f;

#pragma unroll
    for (int kb = 0; kb < CDIM; kb += 64) {
        if (kb) __syncthreads();
#pragma unroll
        for (int e = 0; e < 4; e++) {
            int idx = tid + e * 256;
            int r = idx >> 3, c8 = idx & 7;
            *reinterpret_cast<uint4*>(sA + r * SMK + c8 * 8) =
                *reinterpret_cast<const uint4*>(A + (size_t)(i0 + r) * CDIM + kb + c8 * 8);
            *reinterpret_cast<uint4*>(sB + r * SMK + c8 * 8) =
                *reinterpret_cast<const uint4*>(Bm + (size_t)(j0 + r) * CDIM + kb + c8 * 8);
        }
        __syncthreads();

#pragma unroll
        for (int ks = 0; ks < 4; ks++) {
            int k0 = ks * 16;
            uint32_t afr[2][4];
#pragma unroll
            for (int mt = 0; mt < 2; mt++) {
                int row = wm + mt * 16 + (lane & 15);
                int col = k0 + ((lane >> 4) << 3);
                uint32_t addr = (uint32_t)__cvta_generic_to_shared(sA + row * SMK + col);
                ldsm4(afr[mt], addr);
            }
            uint32_t bfr[8][2];
#pragma unroll
            for (int p = 0; p < 4; p++) {
                int l4 = lane & 7, g = lane >> 3;
                int row = wn + p * 16 + ((g >> 1) << 3) + l4;
                int col = k0 + ((g & 1) << 3);
                uint32_t addr = (uint32_t)__cvta_generic_to_shared(sB + row * SMK + col);
                uint32_t t4[4];
                ldsm4(t4, addr);
                bfr[2 * p][0] = t4[0]; bfr[2 * p][1] = t4[1];
                bfr[2 * p + 1][0] = t4[2]; bfr[2 * p + 1][1] = t4[3];
            }
#pragma unroll
            for (int mt = 0; mt < 2; mt++)
#pragma unroll
                for (int nt = 0; nt < 8; nt++)
                    mma16816(acc[mt][nt], afr[mt], bfr[nt]);
        }
    }
    __syncthreads();

    __half* sO = smem;
#pragma unroll
    for (int mt = 0; mt < 2; mt++) {
#pragma unroll
        for (int nt = 0; nt < 8; nt++) {
            float e0 = fexpf(fminf(fmaxf(acc[mt][nt][0] * itp, -50.0f), 50.0f));
            float e1 = fexpf(fminf(fmaxf(acc[mt][nt][1] * itp, -50.0f), 50.0f));
            float e2 = fexpf(fminf(fmaxf(acc[mt][nt][2] * itp, -50.0f), 50.0f));
            float e3 = fexpf(fminf(fmaxf(acc[mt][nt][3] * itp, -50.0f), 50.0f));
            int row  = wm + mt * 16 + (lane >> 2);
            int colh = wn + nt * 8 + ((lane & 3) << 1);
            *reinterpret_cast<__half2*>(sO + row * SOUTS + colh)       = __floats2half2_rn(e0, e1);
            *reinterpret_cast<__half2*>(sO + (row + 8) * SOUTS + colh) = __floats2half2_rn(e2, e3);
        }
    }
    __syncthreads();

    __half* Eb = g_E + ((size_t)b << 24);
#pragma unroll
    for (int e = 0; e < 8; e++) {
        int idx = tid + e * 256;
        int r = idx >> 4, c = idx & 15;
        *reinterpret_cast<uint4*>(Eb + (size_t)(i0 + r) * NPTS + j0 + c * 8) =
            *reinterpret_cast<uint4*>(sO + r * SOUTS + c * 8);
    }
}

// ---------------------------------------------------------------------------
// Sinkhorn stripe: 16 rows, warp per row; phase 2 re-reads stripe from L2.
// grid (256, BATCH), 512 threads, only 16 KB smem (c vector).
// ---------------------------------------------------------------------------
__global__ __launch_bounds__(512) void sink_stripe(int it) {
    int b = blockIdx.y;
    int i0 = blockIdx.x * STRIPE;
    int tid = threadIdx.x, w = tid >> 5, lane = tid & 31;
    __shared__ __align__(16) float cs[4096];
    __shared__ float rs[STRIPE];

    const float* cg = g_c + b * CSTRIDE;
#pragma unroll
    for (int q = 0; q < 8; q++) cs[tid + q * 512] = cg[tid + q * 512];
    __syncthreads();

    float ed = g_params[1];
    float cN = g_cNa[it * BATCH + b];
    const __half* Eb = g_E + ((size_t)b << 24);

    // phase 1: warp w owns row i0+w
    const __half* Er = Eb + ((size_t)(i0 + w) << 12);
    float sum = 0.0f;
#pragma unroll 4
    for (int ch = 0; ch < 16; ch++) {
        int j = ch * 256 + lane * 8;
        uint4 ev = *reinterpret_cast<const uint4*>(Er + j);
        const __half2* hp = reinterpret_cast<const __half2*>(&ev);
        float4 c0 = *reinterpret_cast<const float4*>(cs + j);
        float4 c1 = *reinterpret_cast<const float4*>(cs + j + 4);
        float2 f0 = __half22float2(hp[0]);
        float2 f1 = __half22float2(hp[1]);
        float2 f2 = __half22float2(hp[2]);
        float2 f3 = __half22float2(hp[3]);
        sum = fmaf(f0.x, c0.x, sum); sum = fmaf(f0.y, c0.y, sum);
        sum = fmaf(f1.x, c0.z, sum); sum = fmaf(f1.y, c0.w, sum);
        sum = fmaf(f2.x, c1.x, sum); sum = fmaf(f2.y, c1.y, sum);
        sum = fmaf(f3.x, c1.z, sum); sum = fmaf(f3.y, c1.w, sum);
    }
#pragma unroll
    for (int o = 16; o; o >>= 1) sum += __shfl_xor_sync(0xffffffffu, sum, o);
    if (lane == 0) {
        float r = (1.0f / 8192.0f) / (sum + ed * cN);
        rs[w] = r;
        g_r[b * CSTRIDE + i0 + w] = r;
    }
    __syncthreads();

    if (tid < STRIPE) {
        float v = rs[tid];
#pragma unroll
        for (int o = 8; o; o >>= 1) v += __shfl_xor_sync(0xffffu, v, o);
        if (tid == 0) atomicAdd(&g_rsumA[it * BATCH + b], v);
    }

    // phase 2: thread owns 8 cols, re-reads the 16 stripe rows (L2-hot)
    float a[8];
#pragma unroll
    for (int q = 0; q < 8; q++) a[q] = 0.0f;
    const __half* Ec = Eb + ((size_t)i0 << 12) + tid * 8;
#pragma unroll
    for (int i = 0; i < STRIPE; i++) {
        uint4 ev = *reinterpret_cast<const uint4*>(Ec + ((size_t)i << 12));
        const __half2* hp = reinterpret_cast<const __half2*>(&ev);
        float r = rs[i];
        float2 f0 = __half22float2(hp[0]);
        float2 f1 = __half22float2(hp[1]);
        float2 f2 = __half22float2(hp[2]);
        float2 f3 = __half22float2(hp[3]);
        a[0] = fmaf(f0.x, r, a[0]); a[1] = fmaf(f0.y, r, a[1]);
        a[2] = fmaf(f1.x, r, a[2]); a[3] = fmaf(f1.y, r, a[3]);
        a[4] = fmaf(f2.x, r, a[4]); a[5] = fmaf(f2.y, r, a[5]);
        a[6] = fmaf(f3.x, r, a[6]); a[7] = fmaf(f3.y, r, a[7]);
    }
    float* cp = g_colpart + (((size_t)b * NSTRIPES + blockIdx.x) << 12) + tid * 8;
    float4 w0 = {a[0], a[1], a[2], a[3]};
    float4 w1 = {a[4], a[5], a[6], a[7]};
    *reinterpret_cast<float4*>(cp)     = w0;
    *reinterpret_cast<float4*>(cp + 4) = w1;
}

// ---------------------------------------------------------------------------
// Finish: sum 256 stripe partials per column (4-way split), update c+scalars.
// grid (64, BATCH), 256 threads: block covers 64 cols, 4 stripe groups.
// ---------------------------------------------------------------------------
__global__ __launch_bounds__(256) void sink_finish(int it) {
    int b = blockIdx.y, tid = threadIdx.x;
    int col = blockIdx.x * 64 + (tid & 63);
    int sg  = tid >> 6;                       // 0..3
    const float* cp = g_colpart + ((size_t)b * NSTRIPES << 12) + col;
    float s = 0.0f;
#pragma unroll 16
    for (int st = sg * 64; st < sg * 64 + 64; st++) s += cp[(size_t)st << 12];
    __shared__ float pr[256];
    pr[tid] = s;
    __syncthreads();

    float ed = g_params[1];
    float rm = 0.5f / (ed * g_sumcA[it * BATCH + b] + g_cNa[it * BATCH + b]);

    if (tid < 64) {
        float v = pr[tid] + pr[tid + 64] + pr[tid + 128] + pr[tid + 192];
        float cj = (1.0f / 8192.0f) / (v + ed * rm);
        g_c[b * CSTRIDE + col] = cj;
        pr[tid] = cj;
    }
    __syncthreads();
    if (tid < 32) {
        float v = pr[tid] + pr[tid + 32];
#pragma unroll
        for (int o = 16; o; o >>= 1) v += __shfl_xor_sync(0xffffffffu, v, o);
        if (tid == 0) {
            atomicAdd(&g_sumcA[(it + 1) * BATCH + b], v);
            if (blockIdx.x == 0)
                g_cNa[(it + 1) * BATCH + b] = 0.5f / (ed * g_rsumA[it * BATCH + b] + rm);
        }
    }
}

// ---------------------------------------------------------------------------
// Stats: 16 rows/block, warp per row; c/px/py staged once in 48 KB smem.
// Per-lane top-8 + register bitonic warp merge (static indices only).
// grid (256, BATCH), 512 threads, 49152 B dynamic smem.
// ---------------------------------------------------------------------------
extern __shared__ __align__(16) unsigned char dy_smem[];

__device__ __forceinline__ bool beats(float av, int ai, float bv, int bi) {
    return (av > bv) || (av == bv && ai < bi);
}

__global__ __launch_bounds__(512) void stats_kernel() {
    int b = blockIdx.y;
    int i0 = blockIdx.x * 16;
    int tid = threadIdx.x, w = tid >> 5, lane = tid & 31;
    float* cs = reinterpret_cast<float*>(dy_smem);
    float* px = cs + 4096;
    float* py = px + 4096;
    const float* cg  = g_c + b * CSTRIDE;
    const float* pxg = g_posBx + b * NPTS;
    const float* pyg = g_posBy + b * NPTS;
#pragma unroll
    for (int q = 0; q < 8; q++) {
        int idx = tid + q * 512;
        cs[idx] = cg[idx];
        px[idx] = pxg[idx];
        py[idx] = pyg[idx];
    }
    __syncthreads();

    int i = i0 + w;
    const __half* Er = g_E + ((size_t)b << 24) + ((size_t)i << 12);
    float rp = g_r[b * CSTRIDE + i];

    float sm = 0.0f, sx = 0.0f, sy = 0.0f;
    float tv[8]; int tix[8];
#pragma unroll
    for (int t = 0; t < 8; t++) { tv[t] = -1.0f; tix[t] = 0x7fffffff; }

#pragma unroll 2
    for (int ch = 0; ch < 16; ch++) {
        int j = ch * 256 + lane * 8;
        uint4 ev = *reinterpret_cast<const uint4*>(Er + j);
        const __half2* hp = reinterpret_cast<const __half2*>(&ev);
        float4 c0 = *reinterpret_cast<const float4*>(cs + j);
        float4 c1 = *reinterpret_cast<const float4*>(cs + j + 4);
        float4 x0 = *reinterpret_cast<const float4*>(px + j);
        float4 x1 = *reinterpret_cast<const float4*>(px + j + 4);
        float4 y0 = *reinterpret_cast<const float4*>(py + j);
        float4 y1 = *reinterpret_cast<const float4*>(py + j + 4);
        float2 f0 = __half22float2(hp[0]);
        float2 f1 = __half22float2(hp[1]);
        float2 f2 = __half22float2(hp[2]);
        float2 f3 = __half22float2(hp[3]);
        float ps[8] = {f0.x, f0.y, f1.x, f1.y, f2.x, f2.y, f3.x, f3.y};
        float csv[8] = {c0.x, c0.y, c0.z, c0.w, c1.x, c1.y, c1.z, c1.w};
        float xs[8] = {x0.x, x0.y, x0.z, x0.w, x1.x, x1.y, x1.z, x1.w};
        float ys[8] = {y0.x, y0.y, y0.z, y0.w, y1.x, y1.y, y1.z, y1.w};
#pragma unroll
        for (int q = 0; q < 8; q++) {
            float P  = ps[q] * rp * csv[q];
            float ot = fminf(P, 1.0f);
            sm += ot;
            sx = fmaf(ot, xs[q], sx);
            sy = fmaf(ot, ys[q], sy);
            int jj = j + q;
            if (ot > tv[7] || (ot == tv[7] && jj < tix[7])) {
                tv[7] = ot; tix[7] = jj;
#pragma unroll
                for (int q2 = 7; q2 > 0; --q2) {
                    bool sw = beats(tv[q2], tix[q2], tv[q2 - 1], tix[q2 - 1]);
                    if (sw) {
                        float fv = tv[q2]; tv[q2] = tv[q2 - 1]; tv[q2 - 1] = fv;
                        int ii = tix[q2]; tix[q2] = tix[q2 - 1]; tix[q2 - 1] = ii;
                    }
                }
            }
        }
    }

    // warp sum reduce
#pragma unroll
    for (int o = 16; o; o >>= 1) {
        sm += __shfl_xor_sync(0xffffffffu, sm, o);
        sx += __shfl_xor_sync(0xffffffffu, sx, o);
        sy += __shfl_xor_sync(0xffffffffu, sy, o);
    }

    // warp bfly merge of sorted-8 lists (bitonic, static indices)
#pragma unroll
    for (int off = 1; off < 32; off <<= 1) {
        float bv[8]; int bi[8];
#pragma unroll
        for (int t = 0; t < 8; t++) {
            bv[t] = __shfl_xor_sync(0xffffffffu, tv[t], off);
            bi[t] = __shfl_xor_sync(0xffffffffu, tix[t], off);
        }
        // top-8 of merge = elementwise winner of (tv[i], bv[7-i])
#pragma unroll
        for (int t = 0; t < 8; t++) {
            if (beats(bv[7 - t], bi[7 - t], tv[t], tix[t])) {
                tv[t] = bv[7 - t]; tix[t] = bi[7 - t];
            }
        }
        // sort bitonic sequence desc: stages d = 4, 2, 1
#pragma unroll
        for (int d = 4; d; d >>= 1) {
#pragma unroll
            for (int t = 0; t < 8; t++) {
                if (!(t & d)) {
                    int u = t | d;
                    if (beats(tv[u], tix[u], tv[t], tix[t])) {
                        float fv = tv[t]; tv[t] = tv[u]; tv[u] = fv;
                        int ii = tix[t]; tix[t] = tix[u]; tix[u] = ii;
                    }
                }
            }
        }
    }

    if (lane == 0) {
        float rmass = fmaxf(sm, 1e-8f);
        float valid = fminf(fmaxf(rmass * 8192.0f, 0.0f), 1.0f);
        float pr = fminf(fmaxf(tv[0] / rmass, 0.0f), 1.0f);
        float pm = fminf(fmaxf((tv[0] - tv[1]) / rmass, 0.0f), 1.0f);
        float conf = fminf(fmaxf((0.6f * pr + 0.4f * pm) * valid, 0.0f), 1.0f);
        int o = b * NPTS + i;
        g_conf[o] = conf;
        g_base[o * 2]     = sx / rmass;
        g_base[o * 2 + 1] = sy / rmass;
#pragma unroll
        for (int k = 0; k < 8; k++) {
            g_tki[o * 8 + k] = tix[k];
            g_tkl[o * 8 + k] = logf(fmaxf(tv[k], 1e-38f));
        }
    }
}

// ---------------------------------------------------------------------------
// Geo validation: 8-row chunks with halo, grid = BATCH*TOPK*8 = 128 blocks.
// ---------------------------------------------------------------------------
__global__ __launch_bounds__(256) void geo_kernel(const float* __restrict__ posA) {
    int x = blockIdx.x;
    int b  = x >> 6;
    int k  = (x >> 3) & 7;
    int rc = x & 7;
    int tid = threadIdx.x;
    int hbase = rc * 8;
    int hlo = max(hbase - 3, 0);
    int hhi = min(hbase + 10, 63);
    int nrows = hhi - hlo + 1;

    __shared__ float dx[14 * 64], dy[14 * 64];
    for (int t = tid; t < nrows * 64; t += 256) {
        int n = (hlo + (t >> 6)) * 64 + (t & 63);
        int idx = g_tki[(b * NPTS + n) * 8 + k];
        float ax = posA[(size_t)(b * NPTS + n) * 2];
        float ay = posA[(size_t)(b * NPTS + n) * 2 + 1];
        dx[t] = g_posBx[b * NPTS + idx] - ax;
        dy[t] = g_posBy[b * NPTS + idx] - ay;
    }
    __syncthreads();

#pragma unroll
    for (int rep = 0; rep < 2; rep++) {
        int p = rep * 256 + tid;                // 0..511
        int h = hbase + (p >> 6);
        int wcol = p & 63;
        int h0 = max(h - 3, 0), h1 = min(h + 3, 63);
        int w0 = max(wcol - 3, 0), w1 = min(wcol + 3, 63);
        float sxv = 0, syv = 0, sxx = 0, syy = 0;
        for (int hh = h0; hh <= h1; hh++) {
            int base = (hh - hlo) * 64;
            for (int ww = w0; ww <= w1; ww++) {
                float vx = dx[base + ww], vy = dy[base + ww];
                sxv += vx; syv += vy;
                sxx = fmaf(vx, vx, sxx);
                syy = fmaf(vy, vy, syy);
            }
        }
        float inv = 1.0f / (float)((h1 - h0 + 1) * (w1 - w0 + 1));
        float mx = sxv * inv, my = syv * inv;
        float vx = fmaxf(sxx * inv - mx * mx, 0.0f);
        float vy = fmaxf(syy * inv - my * my, 0.0f);
        int n = h * 64 + wcol;
        g_geo[(b * NPTS + n) * 8 + k] = 1.0f / (1.0f + (vx + vy) * 100.0f);
    }
}

// ---------------------------------------------------------------------------
// Final blend (unchanged)
// ---------------------------------------------------------------------------
__global__ void final_kernel(float* __restrict__ out) {
    int t = blockIdx.x * 128 + threadIdx.x;
    int b = t >> 12, n = t & 4095;
    int o = b * NPTS + n;
    float gwv = g_params[2];
    float lc[8]; int id[8];
    float m = -1e30f;
#pragma unroll
    for (int k = 0; k < 8; k++) {
        lc[k] = g_tkl[o * 8 + k] + gwv * g_geo[o * 8 + k];
        id[k] = g_tki[o * 8 + k];
        m = fmaxf(m, lc[k]);
    }
    float ws = 0, rx = 0, ry = 0;
#pragma unroll
    for (int k = 0; k < 8; k++) {
        float w = fexpf(fmaxf(lc[k] - m, -80.0f));
        ws += w;
        rx = fmaf(w, g_posBx[b * NPTS + id[k]], rx);
        ry = fmaf(w, g_posBy[b * NPTS + id[k]], ry);
    }
    rx /= ws; ry /= ws;
    float conf = g_conf[o];
    out[o * 2]     = conf * rx + (1.0f - conf) * g_base[o * 2];
    out[o * 2 + 1] = conf * ry + (1.0f - conf) * g_base[o * 2 + 1];
}

// ---------------------------------------------------------------------------
extern "C" void kernel_launch(void* const* d_in, const int* in_sizes, int n_in,
                              void* d_out, int out_size) {
    const float* fA   = (const float*)d_in[0];
    const float* fB   = (const float*)d_in[1];
    const float* pA   = (const float*)d_in[2];
    const float* pB   = (const float*)d_in[3];
    const float* dust = (const float*)d_in[4];
    const float* geow = (const float*)d_in[5];
    const float* temp = (const float*)d_in[6];
    float* out = (float*)d_out;

    cudaFuncSetAttribute(stats_kernel, cudaFuncAttributeMaxDynamicSharedMemorySize, 49152);

    prep_kernel<<<33, 256>>>(dust, geow, temp, pB);
    norm_kernel<<<2048, 256>>>(fA, fB);
    gemm_exp_kernel<<<dim3(32, 32, BATCH), 256>>>();
    for (int it = 0; it < ITERS; ++it) {
        sink_stripe<<<dim3(NSTRIPES, BATCH), 512>>>(it);
        sink_finish<<<dim3(64, BATCH), 256>>>(it);
    }
    stats_kernel<<<dim3(256, BATCH), 512, 49152>>>();
    geo_kernel<<<128, 256>>>(pA);
    final_kernel<<<64, 128>>>(out);
}